// round 2
// baseline (speedup 1.0000x reference)
#include <cuda_runtime.h>
#include <cuda_bf16.h>

#define Bb 256
#define Ss 512
#define Vv 50000
#define Dd 256
#define Ll 128
#define PAD_T 0
#define BOS_T 1
#define EOS_T 2

// ---------------- device scratch (no allocations allowed) ----------------
__device__ float  g_embW[Vv * Dd];   // emb @ Wout  (51.2 MB)
__device__ float  g_enc[Bb * Dd];
__device__ float  g_mean[Bb * Ll];
__device__ float  g_lv[Bb * Ll];
__device__ float  g_z[Bb * Ll];
__device__ float  g_Wfused[Ll * Dd]; // Wlin @ Wout
__device__ float  g_bfused[Dd];      // blin @ Wout + bout
__device__ float  g_c[Bb * Dd];      // z @ Wfused + bfused
__device__ int    g_len[Bb];
__device__ int    g_mode;            // 0=int32 mask, 1=uint8 mask, 2=float32 mask
__device__ int    g_valid;
__device__ double g_sq;
__device__ double g_kl;

// ---------------- K0: detect mask dtype + zero accumulators ----------------
__global__ void k0_detect(const unsigned* mask_words) {
    __shared__ int any_gt1, any_f32;
    if (threadIdx.x == 0) { any_gt1 = 0; any_f32 = 0; }
    __syncthreads();
    int bad = 0, f32 = 0;
    for (int i = threadIdx.x; i < 32768; i += 256) {
        unsigned v = mask_words[i];
        if (v > 1u) { bad = 1; if (v == 0x3f800000u) f32 = 1; }
    }
    if (bad) atomicOr(&any_gt1, 1);
    if (f32) atomicOr(&any_f32, 1);
    __syncthreads();
    if (threadIdx.x == 0) {
        g_mode = any_gt1 ? (any_f32 ? 2 : 1) : 0;
        g_sq = 0.0; g_kl = 0.0; g_valid = 0;
    }
}

__device__ __forceinline__ int mask_at(const void* m, int idx, int mode) {
    if (mode == 0) return ((const int*)m)[idx] != 0;
    if (mode == 1) return ((const unsigned char*)m)[idx] != 0;
    return ((const float*)m)[idx] != 0.0f;
}

// ---------------- packed f32x2 helpers -------------------------------------
__device__ __forceinline__ unsigned long long dup2(float x) {
    unsigned u = __float_as_uint(x);
    return ((unsigned long long)u << 32) | (unsigned long long)u;
}
#define FMA2(acc, a, b) asm("fma.rn.f32x2 %0, %1, %2, %0;" : "+l"(acc) : "l"(a), "l"(b))
__device__ __forceinline__ float lo32(unsigned long long v) { return __uint_as_float((unsigned)(v & 0xffffffffu)); }
__device__ __forceinline__ float hi32(unsigned long long v) { return __uint_as_float((unsigned)(v >> 32)); }

// ---------------- K4: embW = emb @ Wout  via dual-fp32 FMA ------------------
// 128x128 block tile, 256 threads (16x16), 8x8 per thread.
// acc packed as f32x2 pairs along M. B stored pre-duplicated in smem.
// Per-thread N columns strided: col = tx + 16*j  (conflict-free 64-bit LDS).
__global__ __launch_bounds__(256, 2) void gemm_embW(const float* __restrict__ emb,
                                                    const float* __restrict__ Wout) {
    __shared__ __align__(16) float sA[16][132];               // [k][m]
    __shared__ __align__(16) unsigned long long sBd[16][130]; // [k][n] dup'd
    const int tid = threadIdx.x;
    const int tx = tid & 15, ty = tid >> 4;
    const int row0 = blockIdx.x * 128;
    const int col0 = blockIdx.y * 128;

    const int am = tid >> 1;           // 0..127
    const int ak = (tid & 1) * 8;      // 0 or 8
    const int bk = tid >> 4;           // 0..15
    const int bnb = tid & 15;          // 0..15, cols bnb + 16*j

    unsigned long long acc[4][8];
    #pragma unroll
    for (int i = 0; i < 4; i++)
        #pragma unroll
        for (int j = 0; j < 8; j++) acc[i][j] = 0ull;

    for (int k0 = 0; k0 < Dd; k0 += 16) {
        // --- load A tile (transpose to sA[k][m]) ---
        int gr = row0 + am;
        float4 a0, a1;
        if (gr < Vv) {
            const float* ap = emb + (size_t)gr * Dd + k0 + ak;
            a0 = *(const float4*)ap;
            a1 = *(const float4*)(ap + 4);
        } else {
            a0 = make_float4(0.f, 0.f, 0.f, 0.f);
            a1 = a0;
        }
        sA[ak + 0][am] = a0.x; sA[ak + 1][am] = a0.y;
        sA[ak + 2][am] = a0.z; sA[ak + 3][am] = a0.w;
        sA[ak + 4][am] = a1.x; sA[ak + 5][am] = a1.y;
        sA[ak + 6][am] = a1.z; sA[ak + 7][am] = a1.w;
        // --- load B tile, duplicated ---
        const float* bp = Wout + (size_t)(k0 + bk) * Dd + col0 + bnb;
        #pragma unroll
        for (int j = 0; j < 8; j++)
            sBd[bk][bnb + 16 * j] = dup2(bp[16 * j]);
        __syncthreads();
        #pragma unroll
        for (int kk = 0; kk < 16; kk++) {
            ulonglong2 ap01 = *(const ulonglong2*)&sA[kk][ty * 8];
            ulonglong2 ap23 = *(const ulonglong2*)&sA[kk][ty * 8 + 4];
            unsigned long long apair[4] = {ap01.x, ap01.y, ap23.x, ap23.y};
            unsigned long long bdup[8];
            #pragma unroll
            for (int j = 0; j < 8; j++) bdup[j] = sBd[kk][tx + 16 * j];
            #pragma unroll
            for (int i = 0; i < 4; i++)
                #pragma unroll
                for (int j = 0; j < 8; j++)
                    FMA2(acc[i][j], apair[i], bdup[j]);
        }
        __syncthreads();
    }
    // --- store: rows row0+ty*8+2i(+1), cols col0+tx+16j ---
    #pragma unroll
    for (int i = 0; i < 4; i++) {
        int r0 = row0 + ty * 8 + 2 * i;
        if (r0 < Vv) {
            float* c0 = g_embW + (size_t)r0 * Dd + col0 + tx;
            #pragma unroll
            for (int j = 0; j < 8; j++) c0[16 * j] = lo32(acc[i][j]);
        }
        if (r0 + 1 < Vv) {
            float* c1 = g_embW + (size_t)(r0 + 1) * Dd + col0 + tx;
            #pragma unroll
            for (int j = 0; j < 8; j++) c1[16 * j] = hi32(acc[i][j]);
        }
    }
}

// ---------------- generic small GEMM: C[M,N] = A[M,K]@B[K,N] (+bias) -------
// 64x64 tiles, 256 threads, 4x4 per thread. M,N multiples of 64; K of 16.
__global__ void gemm64(const float* __restrict__ A, const float* __restrict__ B,
                       const float* __restrict__ bias, float* __restrict__ C,
                       int M, int N, int K, int use_gbf) {
    __shared__ __align__(16) float sA[16][68];
    __shared__ __align__(16) float sB[16][64];
    const int tid = threadIdx.x;
    const int tx = tid & 15, ty = tid >> 4;
    const int row0 = blockIdx.x * 64;
    const int col0 = blockIdx.y * 64;
    const int lm = tid >> 2, lk4 = (tid & 3) * 4;
    const int bk = tid >> 4, bn4 = (tid & 15) * 4;

    float acc[4][4];
    #pragma unroll
    for (int i = 0; i < 4; i++)
        #pragma unroll
        for (int j = 0; j < 4; j++) acc[i][j] = 0.0f;

    for (int k0 = 0; k0 < K; k0 += 16) {
        float4 av = *(const float4*)(A + (size_t)(row0 + lm) * K + k0 + lk4);
        sA[lk4 + 0][lm] = av.x; sA[lk4 + 1][lm] = av.y;
        sA[lk4 + 2][lm] = av.z; sA[lk4 + 3][lm] = av.w;
        *(float4*)&sB[bk][bn4] = *(const float4*)(B + (size_t)(k0 + bk) * N + col0 + bn4);
        __syncthreads();
        #pragma unroll
        for (int kk = 0; kk < 16; kk++) {
            float4 a = *(const float4*)&sA[kk][ty * 4];
            float4 b = *(const float4*)&sB[kk][tx * 4];
            float av_[4] = {a.x, a.y, a.z, a.w};
            float bv_[4] = {b.x, b.y, b.z, b.w};
            #pragma unroll
            for (int i = 0; i < 4; i++)
                #pragma unroll
                for (int j = 0; j < 4; j++)
                    acc[i][j] += av_[i] * bv_[j];
        }
        __syncthreads();
    }
    const float* bs = use_gbf ? g_bfused : bias;
    float badd[4] = {0.f, 0.f, 0.f, 0.f};
    if (bs) {
        #pragma unroll
        for (int j = 0; j < 4; j++) badd[j] = bs[col0 + tx * 4 + j];
    }
    #pragma unroll
    for (int i = 0; i < 4; i++) {
        float4 v = make_float4(acc[i][0] + badd[0], acc[i][1] + badd[1],
                               acc[i][2] + badd[2], acc[i][3] + badd[3]);
        *(float4*)(C + (size_t)(row0 + ty * 4 + i) * N + col0 + tx * 4) = v;
    }
}

// ---------------- K2: enc[b,:] = masked mean of (emb[tok]+emb[parent]) ----
__global__ void enc_kernel(const int* __restrict__ vocab,
                           const int* __restrict__ order,
                           const void* __restrict__ mask,
                           const float* __restrict__ emb) {
    const int b = blockIdx.x;
    const int tid = threadIdx.x;
    const int w = tid >> 5, lane = tid & 31;
    const int mode = g_mode;

    __shared__ int sred[256];
    __shared__ int s_len;

    int cnt = 0;
    for (int i = tid; i < Ss; i += 256) cnt += mask_at(mask, b * Ss + i, mode);
    sred[tid] = cnt;
    __syncthreads();
    for (int st = 128; st > 0; st >>= 1) {
        if (tid < st) sred[tid] += sred[tid + st];
        __syncthreads();
    }
    if (tid == 0) {
        int len = sred[0];
        s_len = len;
        g_len[b] = len;
        int nb = (len < Ss) ? len + 1 : Ss + 1;
        atomicAdd(&g_valid, nb);
    }
    __syncthreads();
    const int len = s_len;

    float a0 = 0, a1 = 0, a2 = 0, a3 = 0, a4 = 0, a5 = 0, a6 = 0, a7 = 0;
    for (int s = w; s < len; s += 8) {
        int tok = vocab[b * Ss + s];
        int oi = order[(size_t)(b * Ss + s) * 6];
        if (oi == -1) oi = BOS_T;
        int p;
        if (s == 0) p = BOS_T;
        else        p = (oi < len) ? vocab[b * Ss + oi] : PAD_T;
        const float* r1 = emb + (size_t)tok * Dd + lane * 8;
        const float* r2 = emb + (size_t)p   * Dd + lane * 8;
        float4 x0 = *(const float4*)r1;
        float4 x1 = *(const float4*)(r1 + 4);
        float4 y0 = *(const float4*)r2;
        float4 y1 = *(const float4*)(r2 + 4);
        a0 += x0.x + y0.x; a1 += x0.y + y0.y; a2 += x0.z + y0.z; a3 += x0.w + y0.w;
        a4 += x1.x + y1.x; a5 += x1.y + y1.y; a6 += x1.z + y1.z; a7 += x1.w + y1.w;
    }
    __shared__ float s_acc[8][256];
    float* dst = &s_acc[w][lane * 8];
    dst[0] = a0; dst[1] = a1; dst[2] = a2; dst[3] = a3;
    dst[4] = a4; dst[5] = a5; dst[6] = a6; dst[7] = a7;
    __syncthreads();
    float v = 0;
    #pragma unroll
    for (int ww = 0; ww < 8; ww++) v += s_acc[ww][tid];
    g_enc[b * Dd + tid] = v / (float)len;
}

// ---------------- bfused = blin @ Wout + bout ------------------------------
__global__ void bfused_kernel(const float* __restrict__ blin,
                              const float* __restrict__ Wout,
                              const float* __restrict__ bout) {
    __shared__ float sb[Dd];
    const int t = threadIdx.x;
    sb[t] = blin[t & (Ll - 1)];   // only first Ll used
    __syncthreads();
    float v = bout[t];
    #pragma unroll 4
    for (int k = 0; k < Dd; k++) v += ((k < Ll) ? sb[k] : 0.0f) * 0.0f; // placeholder avoided below
    // recompute properly (blin has Ll elements; Wlin@Wout uses Wfused; bfused uses blin@Wout? No:
    // memory = z@Wlin + blin ; c = memory@Wout + bout = z@(Wlin@Wout) + blin@Wout + bout
    v = bout[t];
    #pragma unroll 4
    for (int k = 0; k < Dd; k++) v += sb[k] * Wout[(size_t)k * Dd + t];
    g_bfused[t] = v;
}

// ---------------- z + kl ----------------------------------------------------
__global__ void zkl_kernel(const float* __restrict__ eps) {
    const int b = blockIdx.x, t = threadIdx.x;  // 128 threads
    float mean = g_mean[b * Ll + t];
    float lv   = g_lv[b * Ll + t];
    g_z[b * Ll + t] = mean + eps[b * Ll + t] * expf(0.5f * lv);
    float klp = 1.0f + lv - mean * mean - expf(lv);
    #pragma unroll
    for (int off = 16; off > 0; off >>= 1)
        klp += __shfl_xor_sync(0xffffffffu, klp, off);
    __shared__ float sw[4];
    if ((t & 31) == 0) sw[t >> 5] = klp;
    __syncthreads();
    if (t == 0) atomicAdd(&g_kl, (double)(sw[0] + sw[1] + sw[2] + sw[3]));
}

// ---------------- K5: token loss reduction --------------------------------
__global__ void loss_kernel(const int* __restrict__ vocab,
                            const float* __restrict__ emb) {
    const int b = blockIdx.x;
    const int chunk = blockIdx.y;   // 0..7
    const int tid = threadIdx.x;
    const int w = tid >> 5, lane = tid & 31;
    const int len = g_len[b];
    const int nb = (len < Ss) ? len + 1 : Ss + 1;

    const float* crow = g_c + b * Dd + lane * 8;
    float4 c0 = *(const float4*)crow;
    float4 c1 = *(const float4*)(crow + 4);

    float ss = 0.0f;
    for (int s = chunk * 8 + w; s < nb; s += 64) {
        int u = (s == 0) ? BOS_T : vocab[b * Ss + s - 1];
        int v;
        if (s < len) v = vocab[b * Ss + s];
        else         v = (len < Ss) ? EOS_T : BOS_T;   // roll-wrap when len==S
        const float* ap = g_embW + (size_t)u * Dd + lane * 8;
        const float* tp = emb    + (size_t)v * Dd + lane * 8;
        float4 x0 = *(const float4*)ap;
        float4 x1 = *(const float4*)(ap + 4);
        float4 y0 = *(const float4*)tp;
        float4 y1 = *(const float4*)(tp + 4);
        float d0 = x0.x + c0.x - y0.x; ss += d0 * d0;
        float d1 = x0.y + c0.y - y0.y; ss += d1 * d1;
        float d2 = x0.z + c0.z - y0.z; ss += d2 * d2;
        float d3 = x0.w + c0.w - y0.w; ss += d3 * d3;
        float d4 = x1.x + c1.x - y1.x; ss += d4 * d4;
        float d5 = x1.y + c1.y - y1.y; ss += d5 * d5;
        float d6 = x1.z + c1.z - y1.z; ss += d6 * d6;
        float d7 = x1.w + c1.w - y1.w; ss += d7 * d7;
    }
    #pragma unroll
    for (int off = 16; off > 0; off >>= 1)
        ss += __shfl_xor_sync(0xffffffffu, ss, off);
    __shared__ float swarp[8];
    if (lane == 0) swarp[w] = ss;
    __syncthreads();
    if (tid == 0) {
        double tot = 0.0;
        #pragma unroll
        for (int i = 0; i < 8; i++) tot += (double)swarp[i];
        atomicAdd(&g_sq, tot);
    }
}

// ---------------- K6: finalize ---------------------------------------------
__global__ void finalize_kernel(float* out) {
    if (threadIdx.x == 0) {
        long long denom = (long long)g_valid * (long long)Dd;
        if (denom < 1) denom = 1;
        out[0] = (float)(g_sq / (double)denom);
        out[1] = (float)(-0.5 * g_kl / (double)Bb);
    }
}

// ---------------- launch ----------------------------------------------------
extern "C" void kernel_launch(void* const* d_in, const int* in_sizes, int n_in,
                              void* d_out, int out_size) {
    (void)in_sizes; (void)n_in; (void)out_size;
    const int*   vocab = (const int*)d_in[0];
    const int*   order = (const int*)d_in[1];
    const void*  mask  = d_in[2];
    const float* eps   = (const float*)d_in[3];
    const float* emb   = (const float*)d_in[4];
    const float* Wm    = (const float*)d_in[5];
    const float* bm    = (const float*)d_in[6];
    const float* Wv    = (const float*)d_in[7];
    const float* bv    = (const float*)d_in[8];
    const float* Wlin  = (const float*)d_in[9];
    const float* blin  = (const float*)d_in[10];
    const float* Wout  = (const float*)d_in[11];
    const float* bout  = (const float*)d_in[12];
    float* out = (float*)d_out;

    float* p_enc;   cudaGetSymbolAddress((void**)&p_enc,   g_enc);
    float* p_mean;  cudaGetSymbolAddress((void**)&p_mean,  g_mean);
    float* p_lv;    cudaGetSymbolAddress((void**)&p_lv,    g_lv);
    float* p_z;     cudaGetSymbolAddress((void**)&p_z,     g_z);
    float* p_Wf;    cudaGetSymbolAddress((void**)&p_Wf,    g_Wfused);
    float* p_c;     cudaGetSymbolAddress((void**)&p_c,     g_c);

    k0_detect<<<1, 256>>>((const unsigned*)mask);
    gemm_embW<<<dim3((Vv + 127) / 128, Dd / 128), 256>>>(emb, Wout);
    enc_kernel<<<Bb, 256>>>(vocab, order, mask, emb);
    gemm64<<<dim3(Bb / 64, Ll / 64), 256>>>(p_enc, Wm, bm, p_mean, Bb, Ll, Dd, 0);
    gemm64<<<dim3(Bb / 64, Ll / 64), 256>>>(p_enc, Wv, bv, p_lv, Bb, Ll, Dd, 0);
    gemm64<<<dim3(Ll / 64, Dd / 64), 256>>>(Wlin, Wout, nullptr, p_Wf, Ll, Dd, Dd, 0);
    bfused_kernel<<<1, 256>>>(blin, Wout, bout);
    zkl_kernel<<<Bb, Ll>>>(eps);
    gemm64<<<dim3(Bb / 64, Dd / 64), 256>>>(p_z, p_Wf, nullptr, p_c, Bb, Dd, Ll, 1);
    loss_kernel<<<dim3(Bb, 8), 256>>>(vocab, emb);
    finalize_kernel<<<1, 32>>>(out);
}

// round 4
// speedup vs baseline: 2.5146x; 2.5146x over previous
#include <cuda_runtime.h>
#include <cuda_bf16.h>
#include <cstdint>

#define Bb 256
#define Ss 512
#define Vv 50000
#define Dd 256
#define Ll 128
#define PAD_T 0
#define BOS_T 1
#define EOS_T 2

// smem padded row: 256 bf16 + 8 pad = 264 elems = 528 bytes
#define ROWB 528
#define A_BYTES (128 * ROWB)            // 67584
#define B_BYTES (256 * ROWB)            // 135168
#define SMEM_GEMM (A_BYTES + B_BYTES)   // 202752

// ---------------- device scratch ----------------
__device__ __nv_bfloat16 g_embWB[(size_t)Vv * Dd];  // emb@Wout in bf16 (25.6MB)
__device__ __nv_bfloat16 g_BT[Dd * Dd];             // bf16 Wout^T  [n][k]
__device__ float  g_enc[Bb * Dd];
__device__ float  g_z[Bb * Ll];
__device__ float  g_Wf[(Ll + 1) * Dd];              // Wlin@Wout ; row 128 = blin@Wout+bout
__device__ float  g_c[Bb * Dd];
__device__ int    g_len[Bb];
__device__ int    g_mode;
__device__ int    g_valid;
__device__ double g_sq;
__device__ double g_kl;

__device__ __forceinline__ uint32_t smem_u32(const void* p) {
    return (uint32_t)__cvta_generic_to_shared(p);
}

// ---------------- K0: detect mask dtype + zero accumulators ----------------
__global__ void k0_detect(const unsigned* mask_words) {
    __shared__ int any_gt1, any_f32;
    if (threadIdx.x == 0) { any_gt1 = 0; any_f32 = 0; }
    __syncthreads();
    int bad = 0, f32 = 0;
    for (int i = threadIdx.x; i < 32768; i += 256) {
        unsigned v = mask_words[i];
        if (v > 1u) { bad = 1; if (v == 0x3f800000u) f32 = 1; }
    }
    if (bad) atomicOr(&any_gt1, 1);
    if (f32) atomicOr(&any_f32, 1);
    __syncthreads();
    if (threadIdx.x == 0) {
        g_mode = any_gt1 ? (any_f32 ? 2 : 1) : 0;
        g_sq = 0.0; g_kl = 0.0; g_valid = 0;
    }
}
__device__ __forceinline__ int mask_at(const void* m, int idx, int mode) {
    if (mode == 0) return ((const int*)m)[idx] != 0;
    if (mode == 1) return ((const unsigned char*)m)[idx] != 0;
    return ((const float*)m)[idx] != 0.0f;
}

// ---------------- prep: g_BT[n][k] = bf16(Wout[k][n]) -----------------------
__global__ void prep_BT(const float* __restrict__ Wout) {
    int idx = blockIdx.x * 256 + threadIdx.x;   // 65536
    int k = idx >> 8, n = idx & 255;
    g_BT[n * Dd + k] = __float2bfloat16(Wout[idx]);
}

// ---------------- gemm_mma: embWB = bf16(emb @ Wout) via mma.sync -----------
// grid 391 CTAs x 256 thr. Per CTA: M=128 rows, N=256, K=256 smem-resident.
__global__ __launch_bounds__(256, 1)
void gemm_mma(const float* __restrict__ emb) {
    extern __shared__ char sm[];
    char* smA = sm;              // [128][264] bf16
    char* smB = sm + A_BYTES;    // [256][264] bf16 (rows = n)

    const int tid  = threadIdx.x;
    const int wid  = tid >> 5, lane = tid & 31;
    const int row0 = blockIdx.x * 128;

    // ---- fill B: coalesced copy of g_BT rows (16B per thread-iter) ----
    {
        const uint4* src = (const uint4*)g_BT;     // 256 rows x 32 uint4
        #pragma unroll
        for (int j = 0; j < 32; j++) {
            int u = tid + j * 256;
            int n = u >> 5, kq = u & 31;
            *(uint4*)(smB + n * ROWB + kq * 16) = src[u];
        }
    }
    // ---- fill A: fp32 -> bf16 ----
    {
        #pragma unroll
        for (int j = 0; j < 32; j++) {
            int u = tid + j * 256;
            int r = u >> 6, q = u & 63;          // r<128, q<64 float4s
            float4 x;
            if (row0 + r < Vv) x = *(const float4*)(emb + (size_t)(row0 + r) * Dd + q * 4);
            else               x = make_float4(0.f, 0.f, 0.f, 0.f);
            __nv_bfloat162 p0 = __floats2bfloat162_rn(x.x, x.y);
            __nv_bfloat162 p1 = __floats2bfloat162_rn(x.z, x.w);
            *(uint2*)(smA + r * ROWB + q * 8) =
                make_uint2(*(uint32_t*)&p0, *(uint32_t*)&p1);
        }
    }
    __syncthreads();

    // ---- compute: warp (wm, wn) covers rows wm*32..+32, cols wn*128..+128 --
    const int wm = wid & 3, wn = wid >> 2;
    float acc[2][16][4];
    #pragma unroll
    for (int mt = 0; mt < 2; mt++)
        #pragma unroll
        for (int nt = 0; nt < 16; nt++)
            #pragma unroll
            for (int e = 0; e < 4; e++) acc[mt][nt][e] = 0.0f;

    // lane-invariant parts of ldmatrix addresses
    uint32_t aAddr[2], bAddr[8];
    {
        int arow = wm * 32 + (lane & 15);
        uint32_t abase = smem_u32(smA) + (lane >> 4) * 16;
        aAddr[0] = abase + (arow) * ROWB;
        aAddr[1] = abase + (arow + 16) * ROWB;
        int brow = wn * 128 + (lane & 7) + ((lane >> 4) << 3);
        uint32_t bbase = smem_u32(smB) + ((lane >> 3) & 1) * 16;
        #pragma unroll
        for (int np = 0; np < 8; np++)
            bAddr[np] = bbase + (brow + np * 16) * ROWB;
    }

    #pragma unroll
    for (int ks = 0; ks < 16; ks++) {
        const uint32_t koff = ks * 32;
        uint32_t a[2][4];
        #pragma unroll
        for (int mt = 0; mt < 2; mt++)
            asm volatile("ldmatrix.sync.aligned.m8n8.x4.shared.b16 {%0,%1,%2,%3}, [%4];"
                         : "=r"(a[mt][0]), "=r"(a[mt][1]), "=r"(a[mt][2]), "=r"(a[mt][3])
                         : "r"(aAddr[mt] + koff));
        #pragma unroll
        for (int np = 0; np < 8; np++) {
            uint32_t b0, b1, b2, b3;
            asm volatile("ldmatrix.sync.aligned.m8n8.x4.shared.b16 {%0,%1,%2,%3}, [%4];"
                         : "=r"(b0), "=r"(b1), "=r"(b2), "=r"(b3)
                         : "r"(bAddr[np] + koff));
            #pragma unroll
            for (int mt = 0; mt < 2; mt++) {
                float* c0 = acc[mt][2 * np];
                asm volatile("mma.sync.aligned.m16n8k16.row.col.f32.bf16.bf16.f32 "
                             "{%0,%1,%2,%3}, {%4,%5,%6,%7}, {%8,%9}, {%0,%1,%2,%3};"
                             : "+f"(c0[0]), "+f"(c0[1]), "+f"(c0[2]), "+f"(c0[3])
                             : "r"(a[mt][0]), "r"(a[mt][1]), "r"(a[mt][2]), "r"(a[mt][3]),
                               "r"(b0), "r"(b1));
                float* c1 = acc[mt][2 * np + 1];
                asm volatile("mma.sync.aligned.m16n8k16.row.col.f32.bf16.bf16.f32 "
                             "{%0,%1,%2,%3}, {%4,%5,%6,%7}, {%8,%9}, {%0,%1,%2,%3};"
                             : "+f"(c1[0]), "+f"(c1[1]), "+f"(c1[2]), "+f"(c1[3])
                             : "r"(a[mt][0]), "r"(a[mt][1]), "r"(a[mt][2]), "r"(a[mt][3]),
                               "r"(b2), "r"(b3));
            }
        }
    }

    // ---- epilogue: fp32 acc -> bf16x2 stores ----
    {
        const int colq = (lane & 3) * 2;
        const int rowq = lane >> 2;
        #pragma unroll
        for (int mt = 0; mt < 2; mt++) {
            int r_lo = row0 + wm * 32 + mt * 16 + rowq;
            int r_hi = r_lo + 8;
            #pragma unroll
            for (int nt = 0; nt < 16; nt++) {
                int col = wn * 128 + nt * 8 + colq;
                __nv_bfloat162 lo = __floats2bfloat162_rn(acc[mt][nt][0], acc[mt][nt][1]);
                __nv_bfloat162 hi = __floats2bfloat162_rn(acc[mt][nt][2], acc[mt][nt][3]);
                if (r_lo < Vv)
                    *(uint32_t*)(g_embWB + (size_t)r_lo * Dd + col) = *(uint32_t*)&lo;
                if (r_hi < Vv)
                    *(uint32_t*)(g_embWB + (size_t)r_hi * Dd + col) = *(uint32_t*)&hi;
            }
        }
    }
}

// ---------------- enc: masked mean of (emb[tok]+emb[parent]) ---------------
__global__ void enc_kernel(const int* __restrict__ vocab,
                           const int* __restrict__ order,
                           const void* __restrict__ mask,
                           const float* __restrict__ emb) {
    const int b = blockIdx.x;
    const int tid = threadIdx.x;
    const int w = tid >> 5, lane = tid & 31;
    const int mode = g_mode;

    __shared__ int sred[256];
    __shared__ int s_len;

    int cnt = 0;
    for (int i = tid; i < Ss; i += 256) cnt += mask_at(mask, b * Ss + i, mode);
    sred[tid] = cnt;
    __syncthreads();
    for (int st = 128; st > 0; st >>= 1) {
        if (tid < st) sred[tid] += sred[tid + st];
        __syncthreads();
    }
    if (tid == 0) {
        int len = sred[0];
        s_len = len;
        g_len[b] = len;
        atomicAdd(&g_valid, (len < Ss) ? len + 1 : Ss + 1);
    }
    __syncthreads();
    const int len = s_len;

    float a0 = 0, a1 = 0, a2 = 0, a3 = 0, a4 = 0, a5 = 0, a6 = 0, a7 = 0;
    for (int s = w; s < len; s += 8) {
        int tok = vocab[b * Ss + s];
        int oi = order[(size_t)(b * Ss + s) * 6];
        if (oi == -1) oi = BOS_T;
        int p;
        if (s == 0) p = BOS_T;
        else        p = (oi < len) ? vocab[b * Ss + oi] : PAD_T;
        const float* r1 = emb + (size_t)tok * Dd + lane * 8;
        const float* r2 = emb + (size_t)p   * Dd + lane * 8;
        float4 x0 = *(const float4*)r1;
        float4 x1 = *(const float4*)(r1 + 4);
        float4 y0 = *(const float4*)r2;
        float4 y1 = *(const float4*)(r2 + 4);
        a0 += x0.x + y0.x; a1 += x0.y + y0.y; a2 += x0.z + y0.z; a3 += x0.w + y0.w;
        a4 += x1.x + y1.x; a5 += x1.y + y1.y; a6 += x1.z + y1.z; a7 += x1.w + y1.w;
    }
    __shared__ float s_acc[8][256];
    float* dst = &s_acc[w][lane * 8];
    dst[0] = a0; dst[1] = a1; dst[2] = a2; dst[3] = a3;
    dst[4] = a4; dst[5] = a5; dst[6] = a6; dst[7] = a7;
    __syncthreads();
    float v = 0;
    #pragma unroll
    for (int ww = 0; ww < 8; ww++) v += s_acc[ww][tid];
    g_enc[b * Dd + tid] = v / (float)len;
}

// ---------------- ka: mean/lv -> z, kl  (grid Bb, block Ll) ----------------
__global__ void ka_kernel(const float* __restrict__ eps,
                          const float* __restrict__ Wm, const float* __restrict__ bm,
                          const float* __restrict__ Wv, const float* __restrict__ bv) {
    const int b = blockIdx.x, t = threadIdx.x;   // 128 threads
    __shared__ float se[Dd];
    se[t]        = g_enc[b * Dd + t];
    se[t + 128]  = g_enc[b * Dd + t + 128];
    __syncthreads();
    float mean = bm[t], lv = bv[t];
    #pragma unroll 8
    for (int d = 0; d < Dd; d++) {
        float e = se[d];
        mean += e * Wm[d * Ll + t];
        lv   += e * Wv[d * Ll + t];
    }
    g_z[b * Ll + t] = mean + eps[b * Ll + t] * expf(0.5f * lv);
    float klp = 1.0f + lv - mean * mean - expf(lv);
    #pragma unroll
    for (int off = 16; off > 0; off >>= 1)
        klp += __shfl_xor_sync(0xffffffffu, klp, off);
    __shared__ float sw[4];
    if ((t & 31) == 0) sw[t >> 5] = klp;
    __syncthreads();
    if (t == 0) atomicAdd(&g_kl, (double)(sw[0] + sw[1] + sw[2] + sw[3]));
}

// ---------------- kwf: Wf = Wlin@Wout (+ bias row) (grid 129, block 256) ---
__global__ void kwf_kernel(const float* __restrict__ Wlin, const float* __restrict__ blin,
                           const float* __restrict__ Wout, const float* __restrict__ bout) {
    const int l = blockIdx.x, d = threadIdx.x;
    __shared__ float sa[Dd];
    sa[d] = (l < Ll) ? Wlin[l * Dd + d] : blin[d];
    __syncthreads();
    float v = (l == Ll) ? bout[d] : 0.0f;
    #pragma unroll 8
    for (int k = 0; k < Dd; k++) v += sa[k] * Wout[(size_t)k * Dd + d];
    g_Wf[l * Dd + d] = v;
}

// ---------------- kc: c = z @ Wf + Wf[128]  (grid Bb, block Dd) ------------
__global__ void kc_kernel() {
    const int b = blockIdx.x, t = threadIdx.x;   // 256 threads
    __shared__ float sz[Ll];
    if (t < Ll) sz[t] = g_z[b * Ll + t];
    __syncthreads();
    float v = g_Wf[Ll * Dd + t];
    #pragma unroll 8
    for (int l = 0; l < Ll; l++) v += sz[l] * g_Wf[l * Dd + t];
    g_c[b * Dd + t] = v;
}

// ---------------- loss reduction -------------------------------------------
__global__ void loss_kernel(const int* __restrict__ vocab,
                            const float* __restrict__ emb) {
    const int b = blockIdx.x;
    const int chunk = blockIdx.y;   // 0..7
    const int tid = threadIdx.x;
    const int w = tid >> 5, lane = tid & 31;
    const int len = g_len[b];
    const int nb = (len < Ss) ? len + 1 : Ss + 1;

    const float* crow = g_c + b * Dd + lane * 8;
    float4 c0 = *(const float4*)crow;
    float4 c1 = *(const float4*)(crow + 4);

    float ss = 0.0f;
    for (int s = chunk * 8 + w; s < nb; s += 64) {
        int u = (s == 0) ? BOS_T : vocab[b * Ss + s - 1];
        int v;
        if (s < len) v = vocab[b * Ss + s];
        else         v = (len < Ss) ? EOS_T : BOS_T;
        uint4 araw = *(const uint4*)(g_embWB + (size_t)u * Dd + lane * 8);
        const __nv_bfloat162* bp = (const __nv_bfloat162*)&araw;
        float2 f0 = __bfloat1622float2(bp[0]);
        float2 f1 = __bfloat1622float2(bp[1]);
        float2 f2 = __bfloat1622float2(bp[2]);
        float2 f3 = __bfloat1622float2(bp[3]);
        const float* tp = emb + (size_t)v * Dd + lane * 8;
        float4 y0 = *(const float4*)tp;
        float4 y1 = *(const float4*)(tp + 4);
        float d0 = f0.x + c0.x - y0.x; ss += d0 * d0;
        float d1 = f0.y + c0.y - y0.y; ss += d1 * d1;
        float d2 = f1.x + c0.z - y0.z; ss += d2 * d2;
        float d3 = f1.y + c0.w - y0.w; ss += d3 * d3;
        float d4 = f2.x + c1.x - y1.x; ss += d4 * d4;
        float d5 = f2.y + c1.y - y1.y; ss += d5 * d5;
        float d6 = f3.x + c1.z - y1.z; ss += d6 * d6;
        float d7 = f3.y + c1.w - y1.w; ss += d7 * d7;
    }
    #pragma unroll
    for (int off = 16; off > 0; off >>= 1)
        ss += __shfl_xor_sync(0xffffffffu, ss, off);
    __shared__ float swarp[8];
    if (lane == 0) swarp[w] = ss;
    __syncthreads();
    if (tid == 0) {
        double tot = 0.0;
        #pragma unroll
        for (int i = 0; i < 8; i++) tot += (double)swarp[i];
        atomicAdd(&g_sq, tot);
    }
}

// ---------------- finalize ---------------------------------------------------
__global__ void finalize_kernel(float* out) {
    if (threadIdx.x == 0) {
        long long denom = (long long)g_valid * (long long)Dd;
        if (denom < 1) denom = 1;
        out[0] = (float)(g_sq / (double)denom);
        out[1] = (float)(-0.5 * g_kl / (double)Bb);
    }
}

// ---------------- launch ----------------------------------------------------
extern "C" void kernel_launch(void* const* d_in, const int* in_sizes, int n_in,
                              void* d_out, int out_size) {
    (void)in_sizes; (void)n_in; (void)out_size;
    const int*   vocab = (const int*)d_in[0];
    const int*   order = (const int*)d_in[1];
    const void*  mask  = d_in[2];
    const float* eps   = (const float*)d_in[3];
    const float* emb   = (const float*)d_in[4];
    const float* Wm    = (const float*)d_in[5];
    const float* bm    = (const float*)d_in[6];
    const float* Wv    = (const float*)d_in[7];
    const float* bv    = (const float*)d_in[8];
    const float* Wlin  = (const float*)d_in[9];
    const float* blin  = (const float*)d_in[10];
    const float* Wout  = (const float*)d_in[11];
    const float* bout  = (const float*)d_in[12];
    float* out = (float*)d_out;

    static int configured = 0;
    if (!configured) {
        cudaFuncSetAttribute(gemm_mma, cudaFuncAttributeMaxDynamicSharedMemorySize, SMEM_GEMM);
        configured = 1;
    }

    k0_detect<<<1, 256>>>((const unsigned*)mask);
    prep_BT<<<256, 256>>>(Wout);
    gemm_mma<<<(Vv + 127) / 128, 256, SMEM_GEMM>>>(emb);
    enc_kernel<<<Bb, 256>>>(vocab, order, mask, emb);
    ka_kernel<<<Bb, Ll>>>(eps, Wm, bm, Wv, bv);
    kwf_kernel<<<Ll + 1, 256>>>(Wlin, blin, Wout, bout);
    kc_kernel<<<Bb, Dd>>>();
    loss_kernel<<<dim3(Bb, 8), 256>>>(vocab, emb);
    finalize_kernel<<<1, 32>>>(out);
}

// round 5
// speedup vs baseline: 2.6053x; 1.0361x over previous
#include <cuda_runtime.h>
#include <cuda_bf16.h>
#include <cstdint>

#define Bb 256
#define Ss 512
#define Vv 50000
#define Dd 256
#define Ll 128
#define PAD_T 0
#define BOS_T 1
#define EOS_T 2

// smem padded row: 256 bf16 + 8 pad = 264 elems = 528 bytes
#define ROWB 528
#define A_BYTES (128 * ROWB)
#define B_BYTES (256 * ROWB)
#define SMEM_GEMM (A_BYTES + B_BYTES)

// ---------------- device scratch ----------------
__device__ __nv_bfloat16 g_embWB[(size_t)Vv * Dd];  // bf16 emb@Wout (25.6MB)
__device__ __nv_bfloat16 g_embB[(size_t)Vv * Dd];   // bf16 emb (25.6MB)
__device__ __nv_bfloat16 g_BT[Dd * Dd];             // bf16 Wout^T [n][k]
__device__ float  g_enc[Bb * Dd];                   // SUM (divide later)
__device__ float  g_z[Bb * Ll];
__device__ float  g_Wf[(Ll + 1) * Dd];
__device__ float  g_c[Bb * Dd];
__device__ int    g_len[Bb];
__device__ int    g_mode;
__device__ int    g_valid;
__device__ double g_sq;
__device__ double g_kl;

__device__ __forceinline__ uint32_t smem_u32(const void* p) {
    return (uint32_t)__cvta_generic_to_shared(p);
}

// ---------------- K0: detect mask dtype, zero enc + accumulators ------------
__global__ void k0_detect(const unsigned* mask_words) {
    // all 64 blocks zero a slice of g_enc
    {
        int i = blockIdx.x * 256 + threadIdx.x;     // 16384 float4 slots
        ((float4*)g_enc)[i] = make_float4(0.f, 0.f, 0.f, 0.f);
    }
    if (blockIdx.x != 0) return;
    __shared__ int any_gt1, any_f32;
    if (threadIdx.x == 0) { any_gt1 = 0; any_f32 = 0; }
    __syncthreads();
    int bad = 0, f32 = 0;
    for (int i = threadIdx.x; i < 32768; i += 256) {
        unsigned v = mask_words[i];
        if (v > 1u) { bad = 1; if (v == 0x3f800000u) f32 = 1; }
    }
    if (bad) atomicOr(&any_gt1, 1);
    if (f32) atomicOr(&any_f32, 1);
    __syncthreads();
    if (threadIdx.x == 0) {
        g_mode = any_gt1 ? (any_f32 ? 2 : 1) : 0;
        g_sq = 0.0; g_kl = 0.0; g_valid = 0;
    }
}
__device__ __forceinline__ int mask_at(const void* m, int idx, int mode) {
    if (mode == 0) return ((const int*)m)[idx] != 0;
    if (mode == 1) return ((const unsigned char*)m)[idx] != 0;
    return ((const float*)m)[idx] != 0.0f;
}

// ---------------- prep: g_BT[n][k] = bf16(Wout[k][n]) -----------------------
__global__ void prep_BT(const float* __restrict__ Wout) {
    int idx = blockIdx.x * 256 + threadIdx.x;
    int k = idx >> 8, n = idx & 255;
    g_BT[n * Dd + k] = __float2bfloat16(Wout[idx]);
}

// ---------------- gemm_mma: embWB = bf16(emb @ Wout); also emits g_embB -----
__global__ __launch_bounds__(256, 1)
void gemm_mma(const float* __restrict__ emb) {
    extern __shared__ char sm[];
    char* smA = sm;
    char* smB = sm + A_BYTES;

    const int tid  = threadIdx.x;
    const int wid  = tid >> 5, lane = tid & 31;
    const int row0 = blockIdx.x * 128;

    // ---- fill B ----
    {
        const uint4* src = (const uint4*)g_BT;
        #pragma unroll
        for (int j = 0; j < 32; j++) {
            int u = tid + j * 256;
            int n = u >> 5, kq = u & 31;
            *(uint4*)(smB + n * ROWB + kq * 16) = src[u];
        }
    }
    // ---- fill A (fp32 -> bf16), also write bf16 emb copy ----
    {
        #pragma unroll
        for (int j = 0; j < 32; j++) {
            int u = tid + j * 256;
            int r = u >> 6, q = u & 63;
            bool valid = (row0 + r) < Vv;
            float4 x;
            if (valid) x = *(const float4*)(emb + (size_t)(row0 + r) * Dd + q * 4);
            else       x = make_float4(0.f, 0.f, 0.f, 0.f);
            __nv_bfloat162 p0 = __floats2bfloat162_rn(x.x, x.y);
            __nv_bfloat162 p1 = __floats2bfloat162_rn(x.z, x.w);
            uint2 pv = make_uint2(*(uint32_t*)&p0, *(uint32_t*)&p1);
            *(uint2*)(smA + r * ROWB + q * 8) = pv;
            if (valid)
                *(uint2*)(g_embB + (size_t)(row0 + r) * Dd + q * 4) = pv;
        }
    }
    __syncthreads();

    const int wm = wid & 3, wn = wid >> 2;
    float acc[2][16][4];
    #pragma unroll
    for (int mt = 0; mt < 2; mt++)
        #pragma unroll
        for (int nt = 0; nt < 16; nt++)
            #pragma unroll
            for (int e = 0; e < 4; e++) acc[mt][nt][e] = 0.0f;

    uint32_t aAddr[2], bAddr[8];
    {
        int arow = wm * 32 + (lane & 15);
        uint32_t abase = smem_u32(smA) + (lane >> 4) * 16;
        aAddr[0] = abase + (arow) * ROWB;
        aAddr[1] = abase + (arow + 16) * ROWB;
        int brow = wn * 128 + (lane & 7) + ((lane >> 4) << 3);
        uint32_t bbase = smem_u32(smB) + ((lane >> 3) & 1) * 16;
        #pragma unroll
        for (int np = 0; np < 8; np++)
            bAddr[np] = bbase + (brow + np * 16) * ROWB;
    }

    #pragma unroll
    for (int ks = 0; ks < 16; ks++) {
        const uint32_t koff = ks * 32;
        uint32_t a[2][4];
        #pragma unroll
        for (int mt = 0; mt < 2; mt++)
            asm volatile("ldmatrix.sync.aligned.m8n8.x4.shared.b16 {%0,%1,%2,%3}, [%4];"
                         : "=r"(a[mt][0]), "=r"(a[mt][1]), "=r"(a[mt][2]), "=r"(a[mt][3])
                         : "r"(aAddr[mt] + koff));
        #pragma unroll
        for (int np = 0; np < 8; np++) {
            uint32_t b0, b1, b2, b3;
            asm volatile("ldmatrix.sync.aligned.m8n8.x4.shared.b16 {%0,%1,%2,%3}, [%4];"
                         : "=r"(b0), "=r"(b1), "=r"(b2), "=r"(b3)
                         : "r"(bAddr[np] + koff));
            #pragma unroll
            for (int mt = 0; mt < 2; mt++) {
                float* c0 = acc[mt][2 * np];
                asm volatile("mma.sync.aligned.m16n8k16.row.col.f32.bf16.bf16.f32 "
                             "{%0,%1,%2,%3}, {%4,%5,%6,%7}, {%8,%9}, {%0,%1,%2,%3};"
                             : "+f"(c0[0]), "+f"(c0[1]), "+f"(c0[2]), "+f"(c0[3])
                             : "r"(a[mt][0]), "r"(a[mt][1]), "r"(a[mt][2]), "r"(a[mt][3]),
                               "r"(b0), "r"(b1));
                float* c1 = acc[mt][2 * np + 1];
                asm volatile("mma.sync.aligned.m16n8k16.row.col.f32.bf16.bf16.f32 "
                             "{%0,%1,%2,%3}, {%4,%5,%6,%7}, {%8,%9}, {%0,%1,%2,%3};"
                             : "+f"(c1[0]), "+f"(c1[1]), "+f"(c1[2]), "+f"(c1[3])
                             : "r"(a[mt][0]), "r"(a[mt][1]), "r"(a[mt][2]), "r"(a[mt][3]),
                               "r"(b2), "r"(b3));
            }
        }
    }

    {
        const int colq = (lane & 3) * 2;
        const int rowq = lane >> 2;
        #pragma unroll
        for (int mt = 0; mt < 2; mt++) {
            int r_lo = row0 + wm * 32 + mt * 16 + rowq;
            int r_hi = r_lo + 8;
            #pragma unroll
            for (int nt = 0; nt < 16; nt++) {
                int col = wn * 128 + nt * 8 + colq;
                __nv_bfloat162 lo = __floats2bfloat162_rn(acc[mt][nt][0], acc[mt][nt][1]);
                __nv_bfloat162 hi = __floats2bfloat162_rn(acc[mt][nt][2], acc[mt][nt][3]);
                if (r_lo < Vv)
                    *(uint32_t*)(g_embWB + (size_t)r_lo * Dd + col) = *(uint32_t*)&lo;
                if (r_hi < Vv)
                    *(uint32_t*)(g_embWB + (size_t)r_hi * Dd + col) = *(uint32_t*)&hi;
            }
        }
    }
}

// ---------------- enc_par: partial masked sums, grid (Bb, 4) ---------------
__global__ void enc_par(const int* __restrict__ vocab,
                        const int* __restrict__ order,
                        const void* __restrict__ mask,
                        const float* __restrict__ emb) {
    const int b = blockIdx.x;
    const int part = blockIdx.y;        // 0..3
    const int tid = threadIdx.x;
    const int w = tid >> 5, lane = tid & 31;
    const int mode = g_mode;

    __shared__ int sred[256];
    __shared__ int s_len;

    int cnt = 0;
    for (int i = tid; i < Ss; i += 256) cnt += mask_at(mask, b * Ss + i, mode);
    sred[tid] = cnt;
    __syncthreads();
    for (int st = 128; st > 0; st >>= 1) {
        if (tid < st) sred[tid] += sred[tid + st];
        __syncthreads();
    }
    if (tid == 0) {
        int len = sred[0];
        s_len = len;
        if (part == 0) {
            g_len[b] = len;
            atomicAdd(&g_valid, (len < Ss) ? len + 1 : Ss + 1);
        }
    }
    __syncthreads();
    const int len = s_len;

    float a0 = 0, a1 = 0, a2 = 0, a3 = 0, a4 = 0, a5 = 0, a6 = 0, a7 = 0;
    for (int s = part * 8 + w; s < len; s += 32) {
        int tok = vocab[b * Ss + s];
        int oi = order[(size_t)(b * Ss + s) * 6];
        if (oi == -1) oi = BOS_T;
        int p;
        if (s == 0) p = BOS_T;
        else        p = (oi < len) ? vocab[b * Ss + oi] : PAD_T;
        const float* r1 = emb + (size_t)tok * Dd + lane * 8;
        const float* r2 = emb + (size_t)p   * Dd + lane * 8;
        float4 x0 = *(const float4*)r1;
        float4 x1 = *(const float4*)(r1 + 4);
        float4 y0 = *(const float4*)r2;
        float4 y1 = *(const float4*)(r2 + 4);
        a0 += x0.x + y0.x; a1 += x0.y + y0.y; a2 += x0.z + y0.z; a3 += x0.w + y0.w;
        a4 += x1.x + y1.x; a5 += x1.y + y1.y; a6 += x1.z + y1.z; a7 += x1.w + y1.w;
    }
    __shared__ float s_acc[8][256];
    float* dst = &s_acc[w][lane * 8];
    dst[0] = a0; dst[1] = a1; dst[2] = a2; dst[3] = a3;
    dst[4] = a4; dst[5] = a5; dst[6] = a6; dst[7] = a7;
    __syncthreads();
    float v = 0;
    #pragma unroll
    for (int ww = 0; ww < 8; ww++) v += s_acc[ww][tid];
    atomicAdd(&g_enc[b * Dd + tid], v);
}

// ---------------- ka: mean/lv -> z, kl  (grid Bb, block Ll) ----------------
__global__ void ka_kernel(const float* __restrict__ eps,
                          const float* __restrict__ Wm, const float* __restrict__ bm,
                          const float* __restrict__ Wv, const float* __restrict__ bv) {
    const int b = blockIdx.x, t = threadIdx.x;   // 128 threads
    __shared__ float se[Dd];
    const float inv = 1.0f / (float)g_len[b];
    se[t]       = g_enc[b * Dd + t] * inv;
    se[t + 128] = g_enc[b * Dd + t + 128] * inv;
    __syncthreads();
    float mean = bm[t], lv = bv[t];
    #pragma unroll 8
    for (int d = 0; d < Dd; d++) {
        float e = se[d];
        mean += e * Wm[d * Ll + t];
        lv   += e * Wv[d * Ll + t];
    }
    g_z[b * Ll + t] = mean + eps[b * Ll + t] * expf(0.5f * lv);
    float klp = 1.0f + lv - mean * mean - expf(lv);
    #pragma unroll
    for (int off = 16; off > 0; off >>= 1)
        klp += __shfl_xor_sync(0xffffffffu, klp, off);
    __shared__ float sw[4];
    if ((t & 31) == 0) sw[t >> 5] = klp;
    __syncthreads();
    if (t == 0) atomicAdd(&g_kl, (double)(sw[0] + sw[1] + sw[2] + sw[3]));
}

// ---------------- kwf: Wf = Wlin@Wout (+ bias row) --------------------------
__global__ void kwf_kernel(const float* __restrict__ Wlin, const float* __restrict__ blin,
                           const float* __restrict__ Wout, const float* __restrict__ bout) {
    const int l = blockIdx.x, d = threadIdx.x;
    __shared__ float sa[Dd];
    sa[d] = (l < Ll) ? Wlin[l * Dd + d] : blin[d];
    __syncthreads();
    float v = (l == Ll) ? bout[d] : 0.0f;
    #pragma unroll 8
    for (int k = 0; k < Dd; k++) v += sa[k] * Wout[(size_t)k * Dd + d];
    g_Wf[l * Dd + d] = v;
}

// ---------------- kc: c = z @ Wf + Wf[128] ----------------------------------
__global__ void kc_kernel() {
    const int b = blockIdx.x, t = threadIdx.x;
    __shared__ float sz[Ll];
    if (t < Ll) sz[t] = g_z[b * Ll + t];
    __syncthreads();
    float v = g_Wf[Ll * Dd + t];
    #pragma unroll 8
    for (int l = 0; l < Ll; l++) v += sz[l] * g_Wf[l * Dd + t];
    g_c[b * Dd + t] = v;
}

// ---------------- loss reduction (bf16 gathers both sides) ------------------
__global__ void loss_kernel(const int* __restrict__ vocab) {
    const int b = blockIdx.x;
    const int chunk = blockIdx.y;   // 0..7
    const int tid = threadIdx.x;
    const int w = tid >> 5, lane = tid & 31;
    const int len = g_len[b];
    const int nb = (len < Ss) ? len + 1 : Ss + 1;

    const float* crow = g_c + b * Dd + lane * 8;
    float4 c0 = *(const float4*)crow;
    float4 c1 = *(const float4*)(crow + 4);

    float ss = 0.0f;
    for (int s = chunk * 8 + w; s < nb; s += 64) {
        int u = (s == 0) ? BOS_T : vocab[b * Ss + s - 1];
        int v;
        if (s < len) v = vocab[b * Ss + s];
        else         v = (len < Ss) ? EOS_T : BOS_T;
        uint4 araw = *(const uint4*)(g_embWB + (size_t)u * Dd + lane * 8);
        uint4 traw = *(const uint4*)(g_embB  + (size_t)v * Dd + lane * 8);
        const __nv_bfloat162* ap = (const __nv_bfloat162*)&araw;
        const __nv_bfloat162* tp = (const __nv_bfloat162*)&traw;
        float2 f0 = __bfloat1622float2(ap[0]);
        float2 f1 = __bfloat1622float2(ap[1]);
        float2 f2 = __bfloat1622float2(ap[2]);
        float2 f3 = __bfloat1622float2(ap[3]);
        float2 t0 = __bfloat1622float2(tp[0]);
        float2 t1 = __bfloat1622float2(tp[1]);
        float2 t2 = __bfloat1622float2(tp[2]);
        float2 t3 = __bfloat1622float2(tp[3]);
        float d0 = f0.x + c0.x - t0.x; ss += d0 * d0;
        float d1 = f0.y + c0.y - t0.y; ss += d1 * d1;
        float d2 = f1.x + c0.z - t1.x; ss += d2 * d2;
        float d3 = f1.y + c0.w - t1.y; ss += d3 * d3;
        float d4 = f2.x + c1.x - t2.x; ss += d4 * d4;
        float d5 = f2.y + c1.y - t2.y; ss += d5 * d5;
        float d6 = f3.x + c1.z - t3.x; ss += d6 * d6;
        float d7 = f3.y + c1.w - t3.y; ss += d7 * d7;
    }
    #pragma unroll
    for (int off = 16; off > 0; off >>= 1)
        ss += __shfl_xor_sync(0xffffffffu, ss, off);
    __shared__ float swarp[8];
    if (lane == 0) swarp[w] = ss;
    __syncthreads();
    if (tid == 0) {
        double tot = 0.0;
        #pragma unroll
        for (int i = 0; i < 8; i++) tot += (double)swarp[i];
        atomicAdd(&g_sq, tot);
    }
}

// ---------------- finalize ---------------------------------------------------
__global__ void finalize_kernel(float* out) {
    if (threadIdx.x == 0) {
        long long denom = (long long)g_valid * (long long)Dd;
        if (denom < 1) denom = 1;
        out[0] = (float)(g_sq / (double)denom);
        out[1] = (float)(-0.5 * g_kl / (double)Bb);
    }
}

// ---------------- launch ----------------------------------------------------
extern "C" void kernel_launch(void* const* d_in, const int* in_sizes, int n_in,
                              void* d_out, int out_size) {
    (void)in_sizes; (void)n_in; (void)out_size;
    const int*   vocab = (const int*)d_in[0];
    const int*   order = (const int*)d_in[1];
    const void*  mask  = d_in[2];
    const float* eps   = (const float*)d_in[3];
    const float* emb   = (const float*)d_in[4];
    const float* Wm    = (const float*)d_in[5];
    const float* bm    = (const float*)d_in[6];
    const float* Wv    = (const float*)d_in[7];
    const float* bv    = (const float*)d_in[8];
    const float* Wlin  = (const float*)d_in[9];
    const float* blin  = (const float*)d_in[10];
    const float* Wout  = (const float*)d_in[11];
    const float* bout  = (const float*)d_in[12];
    float* out = (float*)d_out;

    static cudaStream_t s2 = nullptr;
    static cudaEvent_t ev_fork = nullptr, ev_join = nullptr;
    static int configured = 0;
    if (!configured) {
        cudaFuncSetAttribute(gemm_mma, cudaFuncAttributeMaxDynamicSharedMemorySize, SMEM_GEMM);
        cudaStreamCreateWithFlags(&s2, cudaStreamNonBlocking);
        cudaEventCreateWithFlags(&ev_fork, cudaEventDisableTiming);
        cudaEventCreateWithFlags(&ev_join, cudaEventDisableTiming);
        configured = 1;
    }

    // main stream (stream 0 as seen by harness)
    k0_detect<<<64, 256>>>((const unsigned*)mask);
    cudaEventRecord(ev_fork, 0);

    // side stream: enc chain (independent of the big GEMM)
    cudaStreamWaitEvent(s2, ev_fork, 0);
    enc_par<<<dim3(Bb, 4), 256, 0, s2>>>(vocab, order, mask, emb);
    ka_kernel<<<Bb, Ll, 0, s2>>>(eps, Wm, bm, Wv, bv);
    kwf_kernel<<<Ll + 1, 256, 0, s2>>>(Wlin, blin, Wout, bout);
    kc_kernel<<<Bb, Dd, 0, s2>>>();
    cudaEventRecord(ev_join, s2);

    // main stream: GEMM path
    prep_BT<<<256, 256>>>(Wout);
    gemm_mma<<<(Vv + 127) / 128, 256, SMEM_GEMM>>>(emb);

    cudaStreamWaitEvent(0, ev_join, 0);
    loss_kernel<<<dim3(Bb, 8), 256>>>(vocab);
    finalize_kernel<<<1, 32>>>(out);
}

// round 6
// speedup vs baseline: 3.1186x; 1.1970x over previous
#include <cuda_runtime.h>
#include <cuda_bf16.h>
#include <cstdint>

#define Bb 256
#define Ss 512
#define Vv 50000
#define Dd 256
#define Ll 128
#define PAD_T 0
#define BOS_T 1
#define EOS_T 2

#define ROWB 528
#define A_BYTES (128 * ROWB)
#define B_BYTES (256 * ROWB)
#define SMEM_GEMM (A_BYTES + B_BYTES)

// ---------------- device scratch ----------------
__device__ __nv_bfloat16 g_embWB[(size_t)Vv * Dd];  // bf16 emb@Wout
__device__ __nv_bfloat16 g_embB[(size_t)Vv * Dd];   // bf16 emb
__device__ __nv_bfloat16 g_BT[Dd * Dd];             // bf16 Wout^T [n][k]
__device__ float  g_enc[Bb * Dd];                   // SUM (divide later)
__device__ float  g_c[Bb * Dd];
__device__ int    g_len[Bb];
__device__ int    g_mode;
__device__ int    g_valid;
__device__ double g_sq;
__device__ double g_kl;

__device__ __forceinline__ uint32_t smem_u32(const void* p) {
    return (uint32_t)__cvta_generic_to_shared(p);
}

// ---------------- K0: detect mask dtype, zero enc + accumulators ------------
__global__ void k0_detect(const unsigned* mask_words) {
    {
        int i = blockIdx.x * 256 + threadIdx.x;
        ((float4*)g_enc)[i] = make_float4(0.f, 0.f, 0.f, 0.f);
    }
    if (blockIdx.x != 0) return;
    __shared__ int any_gt1, any_f32;
    if (threadIdx.x == 0) { any_gt1 = 0; any_f32 = 0; }
    __syncthreads();
    int bad = 0, f32 = 0;
    for (int i = threadIdx.x; i < 32768; i += 256) {
        unsigned v = mask_words[i];
        if (v > 1u) { bad = 1; if (v == 0x3f800000u) f32 = 1; }
    }
    if (bad) atomicOr(&any_gt1, 1);
    if (f32) atomicOr(&any_f32, 1);
    __syncthreads();
    if (threadIdx.x == 0) {
        g_mode = any_gt1 ? (any_f32 ? 2 : 1) : 0;
        g_sq = 0.0; g_kl = 0.0; g_valid = 0;
    }
}
__device__ __forceinline__ int mask_at(const void* m, int idx, int mode) {
    if (mode == 0) return ((const int*)m)[idx] != 0;
    if (mode == 1) return ((const unsigned char*)m)[idx] != 0;
    return ((const float*)m)[idx] != 0.0f;
}

// ---------------- prep: g_BT[n][k] = bf16(Wout[k][n]) -----------------------
__global__ void prep_BT(const float* __restrict__ Wout) {
    int idx = blockIdx.x * 256 + threadIdx.x;
    int k = idx >> 8, n = idx & 255;
    g_BT[n * Dd + k] = __float2bfloat16(Wout[idx]);
}

// ---------------- gemm_mma: embWB = bf16(emb @ Wout); also emits g_embB -----
__global__ __launch_bounds__(256, 1)
void gemm_mma(const float* __restrict__ emb) {
    extern __shared__ char sm[];
    char* smA = sm;
    char* smB = sm + A_BYTES;

    const int tid  = threadIdx.x;
    const int wid  = tid >> 5, lane = tid & 31;
    const int row0 = blockIdx.x * 128;

    {
        const uint4* src = (const uint4*)g_BT;
        #pragma unroll
        for (int j = 0; j < 32; j++) {
            int u = tid + j * 256;
            int n = u >> 5, kq = u & 31;
            *(uint4*)(smB + n * ROWB + kq * 16) = src[u];
        }
    }
    {
        #pragma unroll
        for (int j = 0; j < 32; j++) {
            int u = tid + j * 256;
            int r = u >> 6, q = u & 63;
            bool valid = (row0 + r) < Vv;
            float4 x;
            if (valid) x = *(const float4*)(emb + (size_t)(row0 + r) * Dd + q * 4);
            else       x = make_float4(0.f, 0.f, 0.f, 0.f);
            __nv_bfloat162 p0 = __floats2bfloat162_rn(x.x, x.y);
            __nv_bfloat162 p1 = __floats2bfloat162_rn(x.z, x.w);
            uint2 pv = make_uint2(*(uint32_t*)&p0, *(uint32_t*)&p1);
            *(uint2*)(smA + r * ROWB + q * 8) = pv;
            if (valid)
                *(uint2*)(g_embB + (size_t)(row0 + r) * Dd + q * 4) = pv;
        }
    }
    __syncthreads();

    const int wm = wid & 3, wn = wid >> 2;
    float acc[2][16][4];
    #pragma unroll
    for (int mt = 0; mt < 2; mt++)
        #pragma unroll
        for (int nt = 0; nt < 16; nt++)
            #pragma unroll
            for (int e = 0; e < 4; e++) acc[mt][nt][e] = 0.0f;

    uint32_t aAddr[2], bAddr[8];
    {
        int arow = wm * 32 + (lane & 15);
        uint32_t abase = smem_u32(smA) + (lane >> 4) * 16;
        aAddr[0] = abase + (arow) * ROWB;
        aAddr[1] = abase + (arow + 16) * ROWB;
        int brow = wn * 128 + (lane & 7) + ((lane >> 4) << 3);
        uint32_t bbase = smem_u32(smB) + ((lane >> 3) & 1) * 16;
        #pragma unroll
        for (int np = 0; np < 8; np++)
            bAddr[np] = bbase + (brow + np * 16) * ROWB;
    }

    #pragma unroll
    for (int ks = 0; ks < 16; ks++) {
        const uint32_t koff = ks * 32;
        uint32_t a[2][4];
        #pragma unroll
        for (int mt = 0; mt < 2; mt++)
            asm volatile("ldmatrix.sync.aligned.m8n8.x4.shared.b16 {%0,%1,%2,%3}, [%4];"
                         : "=r"(a[mt][0]), "=r"(a[mt][1]), "=r"(a[mt][2]), "=r"(a[mt][3])
                         : "r"(aAddr[mt] + koff));
        #pragma unroll
        for (int np = 0; np < 8; np++) {
            uint32_t b0, b1, b2, b3;
            asm volatile("ldmatrix.sync.aligned.m8n8.x4.shared.b16 {%0,%1,%2,%3}, [%4];"
                         : "=r"(b0), "=r"(b1), "=r"(b2), "=r"(b3)
                         : "r"(bAddr[np] + koff));
            #pragma unroll
            for (int mt = 0; mt < 2; mt++) {
                float* c0 = acc[mt][2 * np];
                asm volatile("mma.sync.aligned.m16n8k16.row.col.f32.bf16.bf16.f32 "
                             "{%0,%1,%2,%3}, {%4,%5,%6,%7}, {%8,%9}, {%0,%1,%2,%3};"
                             : "+f"(c0[0]), "+f"(c0[1]), "+f"(c0[2]), "+f"(c0[3])
                             : "r"(a[mt][0]), "r"(a[mt][1]), "r"(a[mt][2]), "r"(a[mt][3]),
                               "r"(b0), "r"(b1));
                float* c1 = acc[mt][2 * np + 1];
                asm volatile("mma.sync.aligned.m16n8k16.row.col.f32.bf16.bf16.f32 "
                             "{%0,%1,%2,%3}, {%4,%5,%6,%7}, {%8,%9}, {%0,%1,%2,%3};"
                             : "+f"(c1[0]), "+f"(c1[1]), "+f"(c1[2]), "+f"(c1[3])
                             : "r"(a[mt][0]), "r"(a[mt][1]), "r"(a[mt][2]), "r"(a[mt][3]),
                               "r"(b2), "r"(b3));
            }
        }
    }

    {
        const int colq = (lane & 3) * 2;
        const int rowq = lane >> 2;
        #pragma unroll
        for (int mt = 0; mt < 2; mt++) {
            int r_lo = row0 + wm * 32 + mt * 16 + rowq;
            int r_hi = r_lo + 8;
            #pragma unroll
            for (int nt = 0; nt < 16; nt++) {
                int col = wn * 128 + nt * 8 + colq;
                __nv_bfloat162 lo = __floats2bfloat162_rn(acc[mt][nt][0], acc[mt][nt][1]);
                __nv_bfloat162 hi = __floats2bfloat162_rn(acc[mt][nt][2], acc[mt][nt][3]);
                if (r_lo < Vv)
                    *(uint32_t*)(g_embWB + (size_t)r_lo * Dd + col) = *(uint32_t*)&lo;
                if (r_hi < Vv)
                    *(uint32_t*)(g_embWB + (size_t)r_hi * Dd + col) = *(uint32_t*)&hi;
            }
        }
    }
}

// ---------------- enc_par: partial masked sums, grid (Bb, 8) ---------------
__global__ void enc_par(const int* __restrict__ vocab,
                        const int* __restrict__ order,
                        const void* __restrict__ mask,
                        const float* __restrict__ emb) {
    const int b = blockIdx.x;
    const int part = blockIdx.y;        // 0..7
    const int tid = threadIdx.x;
    const int w = tid >> 5, lane = tid & 31;
    const int mode = g_mode;

    __shared__ int sred[256];
    __shared__ int s_len;

    int cnt = 0;
    for (int i = tid; i < Ss; i += 256) cnt += mask_at(mask, b * Ss + i, mode);
    sred[tid] = cnt;
    __syncthreads();
    for (int st = 128; st > 0; st >>= 1) {
        if (tid < st) sred[tid] += sred[tid + st];
        __syncthreads();
    }
    if (tid == 0) {
        int len = sred[0];
        s_len = len;
        if (part == 0) {
            g_len[b] = len;
            atomicAdd(&g_valid, (len < Ss) ? len + 1 : Ss + 1);
        }
    }
    __syncthreads();
    const int len = s_len;

    float a0 = 0, a1 = 0, a2 = 0, a3 = 0, a4 = 0, a5 = 0, a6 = 0, a7 = 0;
    for (int s = part * 8 + w; s < len; s += 64) {
        int tok = vocab[b * Ss + s];
        int oi = order[(size_t)(b * Ss + s) * 6];
        if (oi == -1) oi = BOS_T;
        int p;
        if (s == 0) p = BOS_T;
        else        p = (oi < len) ? vocab[b * Ss + oi] : PAD_T;
        const float* r1 = emb + (size_t)tok * Dd + lane * 8;
        const float* r2 = emb + (size_t)p   * Dd + lane * 8;
        float4 x0 = *(const float4*)r1;
        float4 x1 = *(const float4*)(r1 + 4);
        float4 y0 = *(const float4*)r2;
        float4 y1 = *(const float4*)(r2 + 4);
        a0 += x0.x + y0.x; a1 += x0.y + y0.y; a2 += x0.z + y0.z; a3 += x0.w + y0.w;
        a4 += x1.x + y1.x; a5 += x1.y + y1.y; a6 += x1.z + y1.z; a7 += x1.w + y1.w;
    }
    __shared__ float s_acc[8][256];
    float* dst = &s_acc[w][lane * 8];
    dst[0] = a0; dst[1] = a1; dst[2] = a2; dst[3] = a3;
    dst[4] = a4; dst[5] = a5; dst[6] = a6; dst[7] = a7;
    __syncthreads();
    float v = 0;
    #pragma unroll
    for (int ww = 0; ww < 8; ww++) v += s_acc[ww][tid];
    atomicAdd(&g_enc[b * Dd + tid], v);
}

// ---------------- klat: fused mean/lv -> z,kl -> memory -> c ----------------
// grid Bb, block 256. Warps 0-3 compute mean, warps 4-7 compute log_var.
__global__ void klat_kernel(const float* __restrict__ eps,
                            const float* __restrict__ Wm, const float* __restrict__ bm,
                            const float* __restrict__ Wv, const float* __restrict__ bv,
                            const float* __restrict__ Wlin, const float* __restrict__ blin,
                            const float* __restrict__ Wout, const float* __restrict__ bout) {
    const int b = blockIdx.x, t = threadIdx.x;
    __shared__ float se[Dd];
    __shared__ float smean[Ll], slv[Ll], sz[Ll], smem_[Dd];
    __shared__ float skl[256];

    const float inv = 1.0f / (float)g_len[b];
    se[t] = g_enc[b * Dd + t] * inv;
    __syncthreads();

    // phase 1: mean (t<128) / log_var (t>=128), 4-way ILP
    {
        const int tt = t & (Ll - 1);
        const float* W = (t < Ll) ? Wm : Wv;
        float a0 = 0.f, a1 = 0.f, a2 = 0.f, a3 = 0.f;
        #pragma unroll
        for (int d = 0; d < Dd; d += 4) {
            a0 += se[d + 0] * W[(d + 0) * Ll + tt];
            a1 += se[d + 1] * W[(d + 1) * Ll + tt];
            a2 += se[d + 2] * W[(d + 2) * Ll + tt];
            a3 += se[d + 3] * W[(d + 3) * Ll + tt];
        }
        float r = ((t < Ll) ? bm[tt] : bv[tt]) + (a0 + a1) + (a2 + a3);
        if (t < Ll) smean[tt] = r; else slv[tt] = r;
    }
    __syncthreads();

    // phase 2: z + kl (t<128)
    float klp = 0.0f;
    if (t < Ll) {
        float mean = smean[t], lv = slv[t];
        sz[t] = mean + eps[b * Ll + t] * expf(0.5f * lv);
        klp = 1.0f + lv - mean * mean - expf(lv);
    }
    skl[t] = klp;
    __syncthreads();
    for (int st = 128; st > 0; st >>= 1) {
        if (t < st) skl[t] += skl[t + st];
        __syncthreads();
    }
    if (t == 0) atomicAdd(&g_kl, (double)skl[0]);

    // phase 3: memory[t] = blin[t] + sum_l z[l]*Wlin[l][t]
    {
        float a0 = 0.f, a1 = 0.f, a2 = 0.f, a3 = 0.f;
        #pragma unroll
        for (int l = 0; l < Ll; l += 4) {
            a0 += sz[l + 0] * Wlin[(l + 0) * Dd + t];
            a1 += sz[l + 1] * Wlin[(l + 1) * Dd + t];
            a2 += sz[l + 2] * Wlin[(l + 2) * Dd + t];
            a3 += sz[l + 3] * Wlin[(l + 3) * Dd + t];
        }
        smem_[t] = blin[t] + (a0 + a1) + (a2 + a3);
    }
    __syncthreads();

    // phase 4: c[t] = bout[t] + sum_k memory[k]*Wout[k][t]
    {
        float a0 = 0.f, a1 = 0.f, a2 = 0.f, a3 = 0.f;
        #pragma unroll
        for (int k = 0; k < Dd; k += 4) {
            a0 += smem_[k + 0] * Wout[(size_t)(k + 0) * Dd + t];
            a1 += smem_[k + 1] * Wout[(size_t)(k + 1) * Dd + t];
            a2 += smem_[k + 2] * Wout[(size_t)(k + 2) * Dd + t];
            a3 += smem_[k + 3] * Wout[(size_t)(k + 3) * Dd + t];
        }
        g_c[b * Dd + t] = bout[t] + (a0 + a1) + (a2 + a3);
    }
}

// ---------------- loss reduction (bf16 gathers both sides) ------------------
__global__ void loss_kernel(const int* __restrict__ vocab) {
    const int b = blockIdx.x;
    const int chunk = blockIdx.y;   // 0..7
    const int tid = threadIdx.x;
    const int w = tid >> 5, lane = tid & 31;
    const int len = g_len[b];
    const int nb = (len < Ss) ? len + 1 : Ss + 1;

    const float* crow = g_c + b * Dd + lane * 8;
    float4 c0 = *(const float4*)crow;
    float4 c1 = *(const float4*)(crow + 4);

    float ss = 0.0f;
    for (int s = chunk * 8 + w; s < nb; s += 64) {
        int u = (s == 0) ? BOS_T : vocab[b * Ss + s - 1];
        int v;
        if (s < len) v = vocab[b * Ss + s];
        else         v = (len < Ss) ? EOS_T : BOS_T;
        uint4 araw = *(const uint4*)(g_embWB + (size_t)u * Dd + lane * 8);
        uint4 traw = *(const uint4*)(g_embB  + (size_t)v * Dd + lane * 8);
        const __nv_bfloat162* ap = (const __nv_bfloat162*)&araw;
        const __nv_bfloat162* tp = (const __nv_bfloat162*)&traw;
        float2 f0 = __bfloat1622float2(ap[0]);
        float2 f1 = __bfloat1622float2(ap[1]);
        float2 f2 = __bfloat1622float2(ap[2]);
        float2 f3 = __bfloat1622float2(ap[3]);
        float2 t0 = __bfloat1622float2(tp[0]);
        float2 t1 = __bfloat1622float2(tp[1]);
        float2 t2 = __bfloat1622float2(tp[2]);
        float2 t3 = __bfloat1622float2(tp[3]);
        float d0 = f0.x + c0.x - t0.x; ss += d0 * d0;
        float d1 = f0.y + c0.y - t0.y; ss += d1 * d1;
        float d2 = f1.x + c0.z - t1.x; ss += d2 * d2;
        float d3 = f1.y + c0.w - t1.y; ss += d3 * d3;
        float d4 = f2.x + c1.x - t2.x; ss += d4 * d4;
        float d5 = f2.y + c1.y - t2.y; ss += d5 * d5;
        float d6 = f3.x + c1.z - t3.x; ss += d6 * d6;
        float d7 = f3.y + c1.w - t3.y; ss += d7 * d7;
    }
    #pragma unroll
    for (int off = 16; off > 0; off >>= 1)
        ss += __shfl_xor_sync(0xffffffffu, ss, off);
    __shared__ float swarp[8];
    if (lane == 0) swarp[w] = ss;
    __syncthreads();
    if (tid == 0) {
        double tot = 0.0;
        #pragma unroll
        for (int i = 0; i < 8; i++) tot += (double)swarp[i];
        atomicAdd(&g_sq, tot);
    }
}

// ---------------- finalize ---------------------------------------------------
__global__ void finalize_kernel(float* out) {
    if (threadIdx.x == 0) {
        long long denom = (long long)g_valid * (long long)Dd;
        if (denom < 1) denom = 1;
        out[0] = (float)(g_sq / (double)denom);
        out[1] = (float)(-0.5 * g_kl / (double)Bb);
    }
}

// ---------------- launch ----------------------------------------------------
extern "C" void kernel_launch(void* const* d_in, const int* in_sizes, int n_in,
                              void* d_out, int out_size) {
    (void)in_sizes; (void)n_in; (void)out_size;
    const int*   vocab = (const int*)d_in[0];
    const int*   order = (const int*)d_in[1];
    const void*  mask  = d_in[2];
    const float* eps   = (const float*)d_in[3];
    const float* emb   = (const float*)d_in[4];
    const float* Wm    = (const float*)d_in[5];
    const float* bm    = (const float*)d_in[6];
    const float* Wv    = (const float*)d_in[7];
    const float* bv    = (const float*)d_in[8];
    const float* Wlin  = (const float*)d_in[9];
    const float* blin  = (const float*)d_in[10];
    const float* Wout  = (const float*)d_in[11];
    const float* bout  = (const float*)d_in[12];
    float* out = (float*)d_out;

    static cudaStream_t s2 = nullptr;
    static cudaEvent_t ev_fork = nullptr, ev_join = nullptr;
    static int configured = 0;
    if (!configured) {
        cudaFuncSetAttribute(gemm_mma, cudaFuncAttributeMaxDynamicSharedMemorySize, SMEM_GEMM);
        cudaStreamCreateWithFlags(&s2, cudaStreamNonBlocking);
        cudaEventCreateWithFlags(&ev_fork, cudaEventDisableTiming);
        cudaEventCreateWithFlags(&ev_join, cudaEventDisableTiming);
        configured = 1;
    }

    k0_detect<<<64, 256>>>((const unsigned*)mask);
    cudaEventRecord(ev_fork, 0);

    // side stream: enc chain
    cudaStreamWaitEvent(s2, ev_fork, 0);
    enc_par<<<dim3(Bb, 8), 256, 0, s2>>>(vocab, order, mask, emb);
    klat_kernel<<<Bb, 256, 0, s2>>>(eps, Wm, bm, Wv, bv, Wlin, blin, Wout, bout);
    cudaEventRecord(ev_join, s2);

    // main stream: GEMM path
    prep_BT<<<256, 256>>>(Wout);
    gemm_mma<<<(Vv + 127) / 128, 256, SMEM_GEMM>>>(emb);

    cudaStreamWaitEvent(0, ev_join, 0);
    loss_kernel<<<dim3(Bb, 8), 256>>>(vocab);
    finalize_kernel<<<1, 32>>>(out);
}

// round 7
// speedup vs baseline: 3.2080x; 1.0287x over previous
#include <cuda_runtime.h>
#include <cuda_bf16.h>
#include <cstdint>

#define Bb 256
#define Ss 512
#define Vv 50000
#define Dd 256
#define Ll 128
#define PAD_T 0
#define BOS_T 1
#define EOS_T 2

#define ROWB 528                      // B row bytes (k-major row: 256 bf16 + pad)
#define AROW 144                      // A chunk row bytes (64 bf16 + pad)
#define ACH  (128 * AROW)             // 18432 per A buffer
#define B_BYTES (256 * ROWB)          // 135168
#define SMEM_GEMM (B_BYTES + 2 * ACH) // 172032

// ---------------- device scratch ----------------
__device__ __nv_bfloat16 g_embWB[(size_t)Vv * Dd];  // bf16 emb@Wout
__device__ __nv_bfloat16 g_embB[(size_t)Vv * Dd];   // bf16 emb
__device__ __nv_bfloat16 g_BT[Dd * Dd];             // bf16 Wout (k-major, same layout)
__device__ float  g_enc[Bb * Dd];
__device__ float  g_c[Bb * Dd];
__device__ int    g_len[Bb];
__device__ int    g_mode;
__device__ int    g_valid;
__device__ double g_sq;
__device__ double g_kl;

__device__ __forceinline__ uint32_t smem_u32(const void* p) {
    return (uint32_t)__cvta_generic_to_shared(p);
}

// ---------------- K0: detect mask dtype, zero enc + accumulators ------------
__global__ void k0_detect(const unsigned* mask_words) {
    {
        int i = blockIdx.x * 256 + threadIdx.x;
        ((float4*)g_enc)[i] = make_float4(0.f, 0.f, 0.f, 0.f);
    }
    if (blockIdx.x != 0) return;
    __shared__ int any_gt1, any_f32;
    if (threadIdx.x == 0) { any_gt1 = 0; any_f32 = 0; }
    __syncthreads();
    int bad = 0, f32 = 0;
    for (int i = threadIdx.x; i < 32768; i += 256) {
        unsigned v = mask_words[i];
        if (v > 1u) { bad = 1; if (v == 0x3f800000u) f32 = 1; }
    }
    if (bad) atomicOr(&any_gt1, 1);
    if (f32) atomicOr(&any_f32, 1);
    __syncthreads();
    if (threadIdx.x == 0) {
        g_mode = any_gt1 ? (any_f32 ? 2 : 1) : 0;
        g_sq = 0.0; g_kl = 0.0; g_valid = 0;
    }
}
__device__ __forceinline__ int mask_at(const void* m, int idx, int mode) {
    if (mode == 0) return ((const int*)m)[idx] != 0;
    if (mode == 1) return ((const unsigned char*)m)[idx] != 0;
    return ((const float*)m)[idx] != 0.0f;
}

// ---------------- prep: g_BT = bf16(Wout), same layout (coalesced) ----------
__global__ void prep_BT(const float* __restrict__ Wout) {
    int idx = blockIdx.x * 256 + threadIdx.x;   // 16384 threads
    float4 x = ((const float4*)Wout)[idx];
    __nv_bfloat162 p0 = __floats2bfloat162_rn(x.x, x.y);
    __nv_bfloat162 p1 = __floats2bfloat162_rn(x.z, x.w);
    ((uint2*)g_BT)[idx] = make_uint2(*(uint32_t*)&p0, *(uint32_t*)&p1);
}

// ---------------- gemm_mma: pipelined, 512 threads ---------------------------
__global__ __launch_bounds__(512, 1)
void gemm_mma(const float* __restrict__ emb) {
    extern __shared__ char sm[];
    char* smB = sm;                 // [k=256][ROWB]
    char* smA = sm + B_BYTES;       // 2 x [128][AROW]

    const int tid  = threadIdx.x;
    const int wid  = tid >> 5, lane = tid & 31;
    const int row0 = blockIdx.x * 128;

    // ---- B fill: straight copy of k-major bf16 Wout ----
    {
        const uint4* src = (const uint4*)g_BT;     // 8192 uint4
        #pragma unroll
        for (int j = 0; j < 16; j++) {
            int u = tid + j * 512;
            int kr = u >> 5, kq = u & 31;
            *(uint4*)(smB + kr * ROWB + kq * 16) = src[u];
        }
    }

    float4 stage[4];
    // ---- load chunk 0 ----
    #pragma unroll
    for (int j = 0; j < 4; j++) {
        int u = tid + j * 512;
        int r = u >> 4, q = u & 15;
        stage[j] = (row0 + r < Vv)
                 ? *(const float4*)(emb + (size_t)(row0 + r) * Dd + q * 4)
                 : make_float4(0.f, 0.f, 0.f, 0.f);
    }
    // ---- store chunk 0 (+ g_embB) ----
    #pragma unroll
    for (int j = 0; j < 4; j++) {
        int u = tid + j * 512;
        int r = u >> 4, q = u & 15;
        __nv_bfloat162 p0 = __floats2bfloat162_rn(stage[j].x, stage[j].y);
        __nv_bfloat162 p1 = __floats2bfloat162_rn(stage[j].z, stage[j].w);
        uint2 pv = make_uint2(*(uint32_t*)&p0, *(uint32_t*)&p1);
        *(uint2*)(smA + r * AROW + q * 8) = pv;
        if (row0 + r < Vv)
            *(uint2*)(g_embB + (size_t)(row0 + r) * Dd + q * 4) = pv;
    }
    __syncthreads();

    const int wm = wid & 3, wn = wid >> 2;
    float acc[2][8][4];
    #pragma unroll
    for (int mt = 0; mt < 2; mt++)
        #pragma unroll
        for (int nt = 0; nt < 8; nt++)
            #pragma unroll
            for (int e = 0; e < 4; e++) acc[mt][nt][e] = 0.0f;

    const uint32_t aBase = smem_u32(smA) + (wm * 32 + (lane & 15)) * AROW + (lane >> 4) * 16;
    const uint32_t bBase = smem_u32(smB) + (lane & 15) * ROWB
                         + (wn * 64 + (lane >> 4) * 8) * 2;

    for (int c = 0; c < 4; c++) {
        // issue global loads for next chunk
        if (c < 3) {
            #pragma unroll
            for (int j = 0; j < 4; j++) {
                int u = tid + j * 512;
                int r = u >> 4, q = u & 15;
                stage[j] = (row0 + r < Vv)
                         ? *(const float4*)(emb + (size_t)(row0 + r) * Dd + (c + 1) * 64 + q * 4)
                         : make_float4(0.f, 0.f, 0.f, 0.f);
            }
        }
        // compute chunk c
        const uint32_t abuf = aBase + (c & 1) * ACH;
        const uint32_t bko  = (uint32_t)(c * 64) * ROWB;
        #pragma unroll
        for (int ks = 0; ks < 4; ks++) {
            uint32_t a[2][4];
            #pragma unroll
            for (int mt = 0; mt < 2; mt++)
                asm volatile("ldmatrix.sync.aligned.m8n8.x4.shared.b16 {%0,%1,%2,%3}, [%4];"
                             : "=r"(a[mt][0]), "=r"(a[mt][1]), "=r"(a[mt][2]), "=r"(a[mt][3])
                             : "r"(abuf + mt * 16 * AROW + ks * 32));
            #pragma unroll
            for (int np = 0; np < 4; np++) {
                uint32_t b0, b1, b2, b3;
                asm volatile("ldmatrix.sync.aligned.m8n8.x4.trans.shared.b16 {%0,%1,%2,%3}, [%4];"
                             : "=r"(b0), "=r"(b1), "=r"(b2), "=r"(b3)
                             : "r"(bBase + bko + ks * 16 * ROWB + np * 32));
                #pragma unroll
                for (int mt = 0; mt < 2; mt++) {
                    float* c0 = acc[mt][2 * np];
                    asm volatile("mma.sync.aligned.m16n8k16.row.col.f32.bf16.bf16.f32 "
                                 "{%0,%1,%2,%3}, {%4,%5,%6,%7}, {%8,%9}, {%0,%1,%2,%3};"
                                 : "+f"(c0[0]), "+f"(c0[1]), "+f"(c0[2]), "+f"(c0[3])
                                 : "r"(a[mt][0]), "r"(a[mt][1]), "r"(a[mt][2]), "r"(a[mt][3]),
                                   "r"(b0), "r"(b1));
                    float* c1 = acc[mt][2 * np + 1];
                    asm volatile("mma.sync.aligned.m16n8k16.row.col.f32.bf16.bf16.f32 "
                                 "{%0,%1,%2,%3}, {%4,%5,%6,%7}, {%8,%9}, {%0,%1,%2,%3};"
                                 : "+f"(c1[0]), "+f"(c1[1]), "+f"(c1[2]), "+f"(c1[3])
                                 : "r"(a[mt][0]), "r"(a[mt][1]), "r"(a[mt][2]), "r"(a[mt][3]),
                                   "r"(b2), "r"(b3));
                }
            }
        }
        // store next chunk
        if (c < 3) {
            __syncthreads();
            char* dst = smA + ((c + 1) & 1) * ACH;
            #pragma unroll
            for (int j = 0; j < 4; j++) {
                int u = tid + j * 512;
                int r = u >> 4, q = u & 15;
                __nv_bfloat162 p0 = __floats2bfloat162_rn(stage[j].x, stage[j].y);
                __nv_bfloat162 p1 = __floats2bfloat162_rn(stage[j].z, stage[j].w);
                uint2 pv = make_uint2(*(uint32_t*)&p0, *(uint32_t*)&p1);
                *(uint2*)(dst + r * AROW + q * 8) = pv;
                if (row0 + r < Vv)
                    *(uint2*)(g_embB + (size_t)(row0 + r) * Dd + (c + 1) * 64 + q * 4) = pv;
            }
            __syncthreads();
        }
    }

    // ---- epilogue ----
    {
        const int colq = (lane & 3) * 2;
        const int rowq = lane >> 2;
        #pragma unroll
        for (int mt = 0; mt < 2; mt++) {
            int r_lo = row0 + wm * 32 + mt * 16 + rowq;
            int r_hi = r_lo + 8;
            #pragma unroll
            for (int nt = 0; nt < 8; nt++) {
                int col = wn * 64 + nt * 8 + colq;
                __nv_bfloat162 lo = __floats2bfloat162_rn(acc[mt][nt][0], acc[mt][nt][1]);
                __nv_bfloat162 hi = __floats2bfloat162_rn(acc[mt][nt][2], acc[mt][nt][3]);
                if (r_lo < Vv)
                    *(uint32_t*)(g_embWB + (size_t)r_lo * Dd + col) = *(uint32_t*)&lo;
                if (r_hi < Vv)
                    *(uint32_t*)(g_embWB + (size_t)r_hi * Dd + col) = *(uint32_t*)&hi;
            }
        }
    }
}

// ---------------- enc_par: partial masked sums, grid (Bb, 8) ---------------
__global__ void enc_par(const int* __restrict__ vocab,
                        const int* __restrict__ order,
                        const void* __restrict__ mask,
                        const float* __restrict__ emb) {
    const int b = blockIdx.x;
    const int part = blockIdx.y;
    const int tid = threadIdx.x;
    const int w = tid >> 5, lane = tid & 31;
    const int mode = g_mode;

    __shared__ int sred[256];
    __shared__ int s_len;

    int cnt = 0;
    for (int i = tid; i < Ss; i += 256) cnt += mask_at(mask, b * Ss + i, mode);
    sred[tid] = cnt;
    __syncthreads();
    for (int st = 128; st > 0; st >>= 1) {
        if (tid < st) sred[tid] += sred[tid + st];
        __syncthreads();
    }
    if (tid == 0) {
        int len = sred[0];
        s_len = len;
        if (part == 0) {
            g_len[b] = len;
            atomicAdd(&g_valid, (len < Ss) ? len + 1 : Ss + 1);
        }
    }
    __syncthreads();
    const int len = s_len;

    float a0 = 0, a1 = 0, a2 = 0, a3 = 0, a4 = 0, a5 = 0, a6 = 0, a7 = 0;
    for (int s = part * 8 + w; s < len; s += 64) {
        int tok = vocab[b * Ss + s];
        int oi = order[(size_t)(b * Ss + s) * 6];
        if (oi == -1) oi = BOS_T;
        int p;
        if (s == 0) p = BOS_T;
        else        p = (oi < len) ? vocab[b * Ss + oi] : PAD_T;
        const float* r1 = emb + (size_t)tok * Dd + lane * 8;
        const float* r2 = emb + (size_t)p   * Dd + lane * 8;
        float4 x0 = *(const float4*)r1;
        float4 x1 = *(const float4*)(r1 + 4);
        float4 y0 = *(const float4*)r2;
        float4 y1 = *(const float4*)(r2 + 4);
        a0 += x0.x + y0.x; a1 += x0.y + y0.y; a2 += x0.z + y0.z; a3 += x0.w + y0.w;
        a4 += x1.x + y1.x; a5 += x1.y + y1.y; a6 += x1.z + y1.z; a7 += x1.w + y1.w;
    }
    __shared__ float s_acc[8][256];
    float* dst = &s_acc[w][lane * 8];
    dst[0] = a0; dst[1] = a1; dst[2] = a2; dst[3] = a3;
    dst[4] = a4; dst[5] = a5; dst[6] = a6; dst[7] = a7;
    __syncthreads();
    float v = 0;
    #pragma unroll
    for (int ww = 0; ww < 8; ww++) v += s_acc[ww][tid];
    atomicAdd(&g_enc[b * Dd + tid], v);
}

// ---------------- klat: fused mean/lv -> z,kl -> memory -> c ----------------
__global__ void klat_kernel(const float* __restrict__ eps,
                            const float* __restrict__ Wm, const float* __restrict__ bm,
                            const float* __restrict__ Wv, const float* __restrict__ bv,
                            const float* __restrict__ Wlin, const float* __restrict__ blin,
                            const float* __restrict__ Wout, const float* __restrict__ bout) {
    const int b = blockIdx.x, t = threadIdx.x;
    __shared__ float se[Dd];
    __shared__ float smean[Ll], slv[Ll], sz[Ll], smem_[Dd];
    __shared__ float skl[256];

    const float inv = 1.0f / (float)g_len[b];
    se[t] = g_enc[b * Dd + t] * inv;
    __syncthreads();

    {
        const int tt = t & (Ll - 1);
        const float* W = (t < Ll) ? Wm : Wv;
        float a0 = 0.f, a1 = 0.f, a2 = 0.f, a3 = 0.f;
        #pragma unroll
        for (int d = 0; d < Dd; d += 4) {
            a0 += se[d + 0] * W[(d + 0) * Ll + tt];
            a1 += se[d + 1] * W[(d + 1) * Ll + tt];
            a2 += se[d + 2] * W[(d + 2) * Ll + tt];
            a3 += se[d + 3] * W[(d + 3) * Ll + tt];
        }
        float r = ((t < Ll) ? bm[tt] : bv[tt]) + (a0 + a1) + (a2 + a3);
        if (t < Ll) smean[tt] = r; else slv[tt] = r;
    }
    __syncthreads();

    float klp = 0.0f;
    if (t < Ll) {
        float mean = smean[t], lv = slv[t];
        sz[t] = mean + eps[b * Ll + t] * expf(0.5f * lv);
        klp = 1.0f + lv - mean * mean - expf(lv);
    }
    skl[t] = klp;
    __syncthreads();
    for (int st = 128; st > 0; st >>= 1) {
        if (t < st) skl[t] += skl[t + st];
        __syncthreads();
    }
    if (t == 0) atomicAdd(&g_kl, (double)skl[0]);

    {
        float a0 = 0.f, a1 = 0.f, a2 = 0.f, a3 = 0.f;
        #pragma unroll
        for (int l = 0; l < Ll; l += 4) {
            a0 += sz[l + 0] * Wlin[(l + 0) * Dd + t];
            a1 += sz[l + 1] * Wlin[(l + 1) * Dd + t];
            a2 += sz[l + 2] * Wlin[(l + 2) * Dd + t];
            a3 += sz[l + 3] * Wlin[(l + 3) * Dd + t];
        }
        smem_[t] = blin[t] + (a0 + a1) + (a2 + a3);
    }
    __syncthreads();

    {
        float a0 = 0.f, a1 = 0.f, a2 = 0.f, a3 = 0.f;
        #pragma unroll
        for (int k = 0; k < Dd; k += 4) {
            a0 += smem_[k + 0] * Wout[(size_t)(k + 0) * Dd + t];
            a1 += smem_[k + 1] * Wout[(size_t)(k + 1) * Dd + t];
            a2 += smem_[k + 2] * Wout[(size_t)(k + 2) * Dd + t];
            a3 += smem_[k + 3] * Wout[(size_t)(k + 3) * Dd + t];
        }
        g_c[b * Dd + t] = bout[t] + (a0 + a1) + (a2 + a3);
    }
}

// ---------------- loss reduction ---------------------------------------------
__global__ void loss_kernel(const int* __restrict__ vocab) {
    const int b = blockIdx.x;
    const int chunk = blockIdx.y;
    const int tid = threadIdx.x;
    const int w = tid >> 5, lane = tid & 31;
    const int len = g_len[b];
    const int nb = (len < Ss) ? len + 1 : Ss + 1;

    const float* crow = g_c + b * Dd + lane * 8;
    float4 c0 = *(const float4*)crow;
    float4 c1 = *(const float4*)(crow + 4);

    float ss = 0.0f;
    for (int s = chunk * 8 + w; s < nb; s += 64) {
        int u = (s == 0) ? BOS_T : vocab[b * Ss + s - 1];
        int v;
        if (s < len) v = vocab[b * Ss + s];
        else         v = (len < Ss) ? EOS_T : BOS_T;
        uint4 araw = *(const uint4*)(g_embWB + (size_t)u * Dd + lane * 8);
        uint4 traw = *(const uint4*)(g_embB  + (size_t)v * Dd + lane * 8);
        const __nv_bfloat162* ap = (const __nv_bfloat162*)&araw;
        const __nv_bfloat162* tp = (const __nv_bfloat162*)&traw;
        float2 f0 = __bfloat1622float2(ap[0]);
        float2 f1 = __bfloat1622float2(ap[1]);
        float2 f2 = __bfloat1622float2(ap[2]);
        float2 f3 = __bfloat1622float2(ap[3]);
        float2 t0 = __bfloat1622float2(tp[0]);
        float2 t1 = __bfloat1622float2(tp[1]);
        float2 t2 = __bfloat1622float2(tp[2]);
        float2 t3 = __bfloat1622float2(tp[3]);
        float d0 = f0.x + c0.x - t0.x; ss += d0 * d0;
        float d1 = f0.y + c0.y - t0.y; ss += d1 * d1;
        float d2 = f1.x + c0.z - t1.x; ss += d2 * d2;
        float d3 = f1.y + c0.w - t1.y; ss += d3 * d3;
        float d4 = f2.x + c1.x - t2.x; ss += d4 * d4;
        float d5 = f2.y + c1.y - t2.y; ss += d5 * d5;
        float d6 = f3.x + c1.z - t3.x; ss += d6 * d6;
        float d7 = f3.y + c1.w - t3.y; ss += d7 * d7;
    }
    #pragma unroll
    for (int off = 16; off > 0; off >>= 1)
        ss += __shfl_xor_sync(0xffffffffu, ss, off);
    __shared__ float swarp[8];
    if (lane == 0) swarp[w] = ss;
    __syncthreads();
    if (tid == 0) {
        double tot = 0.0;
        #pragma unroll
        for (int i = 0; i < 8; i++) tot += (double)swarp[i];
        atomicAdd(&g_sq, tot);
    }
}

// ---------------- finalize ---------------------------------------------------
__global__ void finalize_kernel(float* out) {
    if (threadIdx.x == 0) {
        long long denom = (long long)g_valid * (long long)Dd;
        if (denom < 1) denom = 1;
        out[0] = (float)(g_sq / (double)denom);
        out[1] = (float)(-0.5 * g_kl / (double)Bb);
    }
}

// ---------------- launch ----------------------------------------------------
extern "C" void kernel_launch(void* const* d_in, const int* in_sizes, int n_in,
                              void* d_out, int out_size) {
    (void)in_sizes; (void)n_in; (void)out_size;
    const int*   vocab = (const int*)d_in[0];
    const int*   order = (const int*)d_in[1];
    const void*  mask  = d_in[2];
    const float* eps   = (const float*)d_in[3];
    const float* emb   = (const float*)d_in[4];
    const float* Wm    = (const float*)d_in[5];
    const float* bm    = (const float*)d_in[6];
    const float* Wv    = (const float*)d_in[7];
    const float* bv    = (const float*)d_in[8];
    const float* Wlin  = (const float*)d_in[9];
    const float* blin  = (const float*)d_in[10];
    const float* Wout  = (const float*)d_in[11];
    const float* bout  = (const float*)d_in[12];
    float* out = (float*)d_out;

    static cudaStream_t s2 = nullptr;
    static cudaEvent_t ev_fork = nullptr, ev_join = nullptr;
    static int configured = 0;
    if (!configured) {
        cudaFuncSetAttribute(gemm_mma, cudaFuncAttributeMaxDynamicSharedMemorySize, SMEM_GEMM);
        cudaStreamCreateWithFlags(&s2, cudaStreamNonBlocking);
        cudaEventCreateWithFlags(&ev_fork, cudaEventDisableTiming);
        cudaEventCreateWithFlags(&ev_join, cudaEventDisableTiming);
        configured = 1;
    }

    cudaEventRecord(ev_fork, 0);

    // side stream: k0 + enc chain (independent of GEMM)
    cudaStreamWaitEvent(s2, ev_fork, 0);
    k0_detect<<<64, 256, 0, s2>>>((const unsigned*)mask);
    enc_par<<<dim3(Bb, 8), 256, 0, s2>>>(vocab, order, mask, emb);
    klat_kernel<<<Bb, 256, 0, s2>>>(eps, Wm, bm, Wv, bv, Wlin, blin, Wout, bout);
    cudaEventRecord(ev_join, s2);

    // main stream: GEMM path
    prep_BT<<<64, 256>>>(Wout);
    gemm_mma<<<(Vv + 127) / 128, 512, SMEM_GEMM>>>(emb);

    cudaStreamWaitEvent(0, ev_join, 0);
    loss_kernel<<<dim3(Bb, 8), 256>>>(vocab);
    finalize_kernel<<<1, 32>>>(out);
}

// round 8
// speedup vs baseline: 3.4943x; 1.0893x over previous
#include <cuda_runtime.h>
#include <cuda_bf16.h>
#include <cstdint>

#define Bb 256
#define Ss 512
#define Vv 50000
#define Dd 256
#define Ll 128
#define PAD_T 0
#define BOS_T 1
#define EOS_T 2

#define ROWB 528                      // B row bytes (k-major row: 256 bf16 + pad)
#define AROW 144                      // A chunk row bytes (64 bf16 + pad)
#define ACH  (128 * AROW)             // 18432 per A buffer
#define B_BYTES (256 * ROWB)          // 135168
#define SMEM_GEMM (B_BYTES + 2 * ACH) // 172032
#define STG_ROW 144                   // epilogue staging row bytes (64 bf16 + 16 pad)

// ---------------- device scratch ----------------
__device__ __nv_bfloat16 g_embWB[(size_t)Vv * Dd];  // bf16 emb@Wout
__device__ __nv_bfloat16 g_embB[(size_t)Vv * Dd];   // bf16 emb
__device__ float  g_enc[Bb * Dd];
__device__ float  g_c[Bb * Dd];
__device__ int    g_len[Bb];
__device__ int    g_mode;
__device__ int    g_valid;
__device__ int    g_done;
__device__ double g_sq;
__device__ double g_kl;

__device__ __forceinline__ uint32_t smem_u32(const void* p) {
    return (uint32_t)__cvta_generic_to_shared(p);
}

// ---------------- K0: detect mask dtype, zero enc + accumulators ------------
__global__ void k0_detect(const unsigned* mask_words) {
    {
        int i = blockIdx.x * 256 + threadIdx.x;
        ((float4*)g_enc)[i] = make_float4(0.f, 0.f, 0.f, 0.f);
    }
    if (blockIdx.x != 0) return;
    __shared__ int any_gt1, any_f32;
    if (threadIdx.x == 0) { any_gt1 = 0; any_f32 = 0; }
    __syncthreads();
    int bad = 0, f32 = 0;
    for (int i = threadIdx.x; i < 32768; i += 256) {
        unsigned v = mask_words[i];
        if (v > 1u) { bad = 1; if (v == 0x3f800000u) f32 = 1; }
    }
    if (bad) atomicOr(&any_gt1, 1);
    if (f32) atomicOr(&any_f32, 1);
    __syncthreads();
    if (threadIdx.x == 0) {
        g_mode = any_gt1 ? (any_f32 ? 2 : 1) : 0;
        g_sq = 0.0; g_kl = 0.0; g_valid = 0; g_done = 0;
    }
}
__device__ __forceinline__ int mask_at(const void* m, int idx, int mode) {
    if (mode == 0) return ((const int*)m)[idx] != 0;
    if (mode == 1) return ((const unsigned char*)m)[idx] != 0;
    return ((const float*)m)[idx] != 0.0f;
}

// ---------------- gemm_mma: pipelined, 512 threads, B from fp32 Wout --------
__global__ __launch_bounds__(512, 1)
void gemm_mma(const float* __restrict__ emb, const float* __restrict__ Wout) {
    extern __shared__ char sm[];
    char* smB = sm;                 // [k=256][ROWB]
    char* smA = sm + B_BYTES;       // 2 x [128][AROW]

    const int tid  = threadIdx.x;
    const int wid  = tid >> 5, lane = tid & 31;
    const int row0 = blockIdx.x * 128;

    // ---- B fill: fp32 Wout -> bf16 smem (k-major), coalesced ----
    {
        #pragma unroll
        for (int j = 0; j < 32; j++) {
            int u = tid + j * 512;              // < 16384 float4s
            float4 x = ((const float4*)Wout)[u];
            int k  = u >> 6;
            int n0 = (u & 63) * 4;
            __nv_bfloat162 p0 = __floats2bfloat162_rn(x.x, x.y);
            __nv_bfloat162 p1 = __floats2bfloat162_rn(x.z, x.w);
            *(uint2*)(smB + k * ROWB + n0 * 2) = make_uint2(*(uint32_t*)&p0, *(uint32_t*)&p1);
        }
    }

    float4 stage[4];
    // ---- load chunk 0 ----
    #pragma unroll
    for (int j = 0; j < 4; j++) {
        int u = tid + j * 512;
        int r = u >> 4, q = u & 15;
        stage[j] = (row0 + r < Vv)
                 ? *(const float4*)(emb + (size_t)(row0 + r) * Dd + q * 4)
                 : make_float4(0.f, 0.f, 0.f, 0.f);
    }
    #pragma unroll
    for (int j = 0; j < 4; j++) {
        int u = tid + j * 512;
        int r = u >> 4, q = u & 15;
        __nv_bfloat162 p0 = __floats2bfloat162_rn(stage[j].x, stage[j].y);
        __nv_bfloat162 p1 = __floats2bfloat162_rn(stage[j].z, stage[j].w);
        uint2 pv = make_uint2(*(uint32_t*)&p0, *(uint32_t*)&p1);
        *(uint2*)(smA + r * AROW + q * 8) = pv;
        if (row0 + r < Vv)
            *(uint2*)(g_embB + (size_t)(row0 + r) * Dd + q * 4) = pv;
    }
    __syncthreads();

    const int wm = wid & 3, wn = wid >> 2;
    float acc[2][8][4];
    #pragma unroll
    for (int mt = 0; mt < 2; mt++)
        #pragma unroll
        for (int nt = 0; nt < 8; nt++)
            #pragma unroll
            for (int e = 0; e < 4; e++) acc[mt][nt][e] = 0.0f;

    const uint32_t aBase = smem_u32(smA) + (wm * 32 + (lane & 15)) * AROW + (lane >> 4) * 16;
    const uint32_t bBase = smem_u32(smB) + (lane & 15) * ROWB
                         + (wn * 64 + (lane >> 4) * 8) * 2;

    for (int c = 0; c < 4; c++) {
        if (c < 3) {
            #pragma unroll
            for (int j = 0; j < 4; j++) {
                int u = tid + j * 512;
                int r = u >> 4, q = u & 15;
                stage[j] = (row0 + r < Vv)
                         ? *(const float4*)(emb + (size_t)(row0 + r) * Dd + (c + 1) * 64 + q * 4)
                         : make_float4(0.f, 0.f, 0.f, 0.f);
            }
        }
        const uint32_t abuf = aBase + (c & 1) * ACH;
        const uint32_t bko  = (uint32_t)(c * 64) * ROWB;
        #pragma unroll
        for (int ks = 0; ks < 4; ks++) {
            uint32_t a[2][4];
            #pragma unroll
            for (int mt = 0; mt < 2; mt++)
                asm volatile("ldmatrix.sync.aligned.m8n8.x4.shared.b16 {%0,%1,%2,%3}, [%4];"
                             : "=r"(a[mt][0]), "=r"(a[mt][1]), "=r"(a[mt][2]), "=r"(a[mt][3])
                             : "r"(abuf + mt * 16 * AROW + ks * 32));
            #pragma unroll
            for (int np = 0; np < 4; np++) {
                uint32_t b0, b1, b2, b3;
                asm volatile("ldmatrix.sync.aligned.m8n8.x4.trans.shared.b16 {%0,%1,%2,%3}, [%4];"
                             : "=r"(b0), "=r"(b1), "=r"(b2), "=r"(b3)
                             : "r"(bBase + bko + ks * 16 * ROWB + np * 32));
                #pragma unroll
                for (int mt = 0; mt < 2; mt++) {
                    float* c0 = acc[mt][2 * np];
                    asm volatile("mma.sync.aligned.m16n8k16.row.col.f32.bf16.bf16.f32 "
                                 "{%0,%1,%2,%3}, {%4,%5,%6,%7}, {%8,%9}, {%0,%1,%2,%3};"
                                 : "+f"(c0[0]), "+f"(c0[1]), "+f"(c0[2]), "+f"(c0[3])
                                 : "r"(a[mt][0]), "r"(a[mt][1]), "r"(a[mt][2]), "r"(a[mt][3]),
                                   "r"(b0), "r"(b1));
                    float* c1 = acc[mt][2 * np + 1];
                    asm volatile("mma.sync.aligned.m16n8k16.row.col.f32.bf16.bf16.f32 "
                                 "{%0,%1,%2,%3}, {%4,%5,%6,%7}, {%8,%9}, {%0,%1,%2,%3};"
                                 : "+f"(c1[0]), "+f"(c1[1]), "+f"(c1[2]), "+f"(c1[3])
                                 : "r"(a[mt][0]), "r"(a[mt][1]), "r"(a[mt][2]), "r"(a[mt][3]),
                                   "r"(b2), "r"(b3));
                }
            }
        }
        if (c < 3) {
            __syncthreads();
            char* dst = smA + ((c + 1) & 1) * ACH;
            #pragma unroll
            for (int j = 0; j < 4; j++) {
                int u = tid + j * 512;
                int r = u >> 4, q = u & 15;
                __nv_bfloat162 p0 = __floats2bfloat162_rn(stage[j].x, stage[j].y);
                __nv_bfloat162 p1 = __floats2bfloat162_rn(stage[j].z, stage[j].w);
                uint2 pv = make_uint2(*(uint32_t*)&p0, *(uint32_t*)&p1);
                *(uint2*)(dst + r * AROW + q * 8) = pv;
                if (row0 + r < Vv)
                    *(uint2*)(g_embB + (size_t)(row0 + r) * Dd + (c + 1) * 64 + q * 4) = pv;
            }
            __syncthreads();
        }
    }

    // ---- epilogue: stage per-warp 32x64 bf16 tile in smem, dense stores ----
    // Staging reuses smB bytes [wid*32*STG_ROW, +4608) < 73728, which only
    // aliases B rows k<140 — unused after the chunk-2 barrier. Per-warp
    // private region: __syncwarp ordering suffices.
    {
        char* stg = smB + wid * 32 * STG_ROW;
        const int colq = (lane & 3) * 2;
        const int rowq = lane >> 2;
        #pragma unroll
        for (int mt = 0; mt < 2; mt++) {
            #pragma unroll
            for (int nt = 0; nt < 8; nt++) {
                __nv_bfloat162 lo = __floats2bfloat162_rn(acc[mt][nt][0], acc[mt][nt][1]);
                __nv_bfloat162 hi = __floats2bfloat162_rn(acc[mt][nt][2], acc[mt][nt][3]);
                *(uint32_t*)(stg + (mt * 16 + rowq) * STG_ROW + (nt * 8 + colq) * 2) = *(uint32_t*)&lo;
                *(uint32_t*)(stg + (mt * 16 + rowq + 8) * STG_ROW + (nt * 8 + colq) * 2) = *(uint32_t*)&hi;
            }
        }
        __syncwarp();
        #pragma unroll
        for (int p = 0; p < 8; p++) {
            int row = p * 4 + (lane >> 3);
            int q = lane & 7;
            uint4 v = *(const uint4*)(stg + row * STG_ROW + q * 16);
            int gr = row0 + wm * 32 + row;
            if (gr < Vv)
                *(uint4*)(g_embWB + (size_t)gr * Dd + wn * 64 + q * 8) = v;
        }
    }
}

// ---------------- enc_par: partial masked sums, grid (Bb, 8) ---------------
__global__ void enc_par(const int* __restrict__ vocab,
                        const int* __restrict__ order,
                        const void* __restrict__ mask,
                        const float* __restrict__ emb) {
    const int b = blockIdx.x;
    const int part = blockIdx.y;
    const int tid = threadIdx.x;
    const int w = tid >> 5, lane = tid & 31;
    const int mode = g_mode;

    __shared__ int sred[256];
    __shared__ int s_len;

    int cnt = 0;
    for (int i = tid; i < Ss; i += 256) cnt += mask_at(mask, b * Ss + i, mode);
    sred[tid] = cnt;
    __syncthreads();
    for (int st = 128; st > 0; st >>= 1) {
        if (tid < st) sred[tid] += sred[tid + st];
        __syncthreads();
    }
    if (tid == 0) {
        int len = sred[0];
        s_len = len;
        if (part == 0) {
            g_len[b] = len;
            atomicAdd(&g_valid, (len < Ss) ? len + 1 : Ss + 1);
        }
    }
    __syncthreads();
    const int len = s_len;

    float a0 = 0, a1 = 0, a2 = 0, a3 = 0, a4 = 0, a5 = 0, a6 = 0, a7 = 0;
    for (int s = part * 8 + w; s < len; s += 64) {
        int tok = vocab[b * Ss + s];
        int oi = order[(size_t)(b * Ss + s) * 6];
        if (oi == -1) oi = BOS_T;
        int p;
        if (s == 0) p = BOS_T;
        else        p = (oi < len) ? vocab[b * Ss + oi] : PAD_T;
        const float* r1 = emb + (size_t)tok * Dd + lane * 8;
        const float* r2 = emb + (size_t)p   * Dd + lane * 8;
        float4 x0 = *(const float4*)r1;
        float4 x1 = *(const float4*)(r1 + 4);
        float4 y0 = *(const float4*)r2;
        float4 y1 = *(const float4*)(r2 + 4);
        a0 += x0.x + y0.x; a1 += x0.y + y0.y; a2 += x0.z + y0.z; a3 += x0.w + y0.w;
        a4 += x1.x + y1.x; a5 += x1.y + y1.y; a6 += x1.z + y1.z; a7 += x1.w + y1.w;
    }
    __shared__ float s_acc[8][256];
    float* dst = &s_acc[w][lane * 8];
    dst[0] = a0; dst[1] = a1; dst[2] = a2; dst[3] = a3;
    dst[4] = a4; dst[5] = a5; dst[6] = a6; dst[7] = a7;
    __syncthreads();
    float v = 0;
    #pragma unroll
    for (int ww = 0; ww < 8; ww++) v += s_acc[ww][tid];
    atomicAdd(&g_enc[b * Dd + tid], v);
}

// ---------------- klat: fused mean/lv -> z,kl -> memory -> c ----------------
__global__ void klat_kernel(const float* __restrict__ eps,
                            const float* __restrict__ Wm, const float* __restrict__ bm,
                            const float* __restrict__ Wv, const float* __restrict__ bv,
                            const float* __restrict__ Wlin, const float* __restrict__ blin,
                            const float* __restrict__ Wout, const float* __restrict__ bout) {
    const int b = blockIdx.x, t = threadIdx.x;
    __shared__ float se[Dd];
    __shared__ float smean[Ll], slv[Ll], sz[Ll], smem_[Dd];
    __shared__ float skl[256];

    const float inv = 1.0f / (float)g_len[b];
    se[t] = g_enc[b * Dd + t] * inv;
    __syncthreads();

    {
        const int tt = t & (Ll - 1);
        const float* W = (t < Ll) ? Wm : Wv;
        float a0 = 0.f, a1 = 0.f, a2 = 0.f, a3 = 0.f;
        #pragma unroll
        for (int d = 0; d < Dd; d += 4) {
            a0 += se[d + 0] * W[(d + 0) * Ll + tt];
            a1 += se[d + 1] * W[(d + 1) * Ll + tt];
            a2 += se[d + 2] * W[(d + 2) * Ll + tt];
            a3 += se[d + 3] * W[(d + 3) * Ll + tt];
        }
        float r = ((t < Ll) ? bm[tt] : bv[tt]) + (a0 + a1) + (a2 + a3);
        if (t < Ll) smean[tt] = r; else slv[tt] = r;
    }
    __syncthreads();

    float klp = 0.0f;
    if (t < Ll) {
        float mean = smean[t], lv = slv[t];
        sz[t] = mean + eps[b * Ll + t] * expf(0.5f * lv);
        klp = 1.0f + lv - mean * mean - expf(lv);
    }
    skl[t] = klp;
    __syncthreads();
    for (int st = 128; st > 0; st >>= 1) {
        if (t < st) skl[t] += skl[t + st];
        __syncthreads();
    }
    if (t == 0) atomicAdd(&g_kl, (double)skl[0]);

    {
        float a0 = 0.f, a1 = 0.f, a2 = 0.f, a3 = 0.f;
        #pragma unroll
        for (int l = 0; l < Ll; l += 4) {
            a0 += sz[l + 0] * Wlin[(l + 0) * Dd + t];
            a1 += sz[l + 1] * Wlin[(l + 1) * Dd + t];
            a2 += sz[l + 2] * Wlin[(l + 2) * Dd + t];
            a3 += sz[l + 3] * Wlin[(l + 3) * Dd + t];
        }
        smem_[t] = blin[t] + (a0 + a1) + (a2 + a3);
    }
    __syncthreads();

    {
        float a0 = 0.f, a1 = 0.f, a2 = 0.f, a3 = 0.f;
        #pragma unroll
        for (int k = 0; k < Dd; k += 4) {
            a0 += smem_[k + 0] * Wout[(size_t)(k + 0) * Dd + t];
            a1 += smem_[k + 1] * Wout[(size_t)(k + 1) * Dd + t];
            a2 += smem_[k + 2] * Wout[(size_t)(k + 2) * Dd + t];
            a3 += smem_[k + 3] * Wout[(size_t)(k + 3) * Dd + t];
        }
        g_c[b * Dd + t] = bout[t] + (a0 + a1) + (a2 + a3);
    }
}

// ---------------- loss reduction + fused finalize ---------------------------
__global__ void loss_kernel(const int* __restrict__ vocab, float* __restrict__ out) {
    const int b = blockIdx.x;
    const int chunk = blockIdx.y;
    const int tid = threadIdx.x;
    const int w = tid >> 5, lane = tid & 31;
    const int len = g_len[b];
    const int nb = (len < Ss) ? len + 1 : Ss + 1;

    const float* crow = g_c + b * Dd + lane * 8;
    float4 c0 = *(const float4*)crow;
    float4 c1 = *(const float4*)(crow + 4);

    float ss = 0.0f;
    for (int s = chunk * 8 + w; s < nb; s += 64) {
        int u = (s == 0) ? BOS_T : vocab[b * Ss + s - 1];
        int v;
        if (s < len) v = vocab[b * Ss + s];
        else         v = (len < Ss) ? EOS_T : BOS_T;
        uint4 araw = *(const uint4*)(g_embWB + (size_t)u * Dd + lane * 8);
        uint4 traw = *(const uint4*)(g_embB  + (size_t)v * Dd + lane * 8);
        const __nv_bfloat162* ap = (const __nv_bfloat162*)&araw;
        const __nv_bfloat162* tp = (const __nv_bfloat162*)&traw;
        float2 f0 = __bfloat1622float2(ap[0]);
        float2 f1 = __bfloat1622float2(ap[1]);
        float2 f2 = __bfloat1622float2(ap[2]);
        float2 f3 = __bfloat1622float2(ap[3]);
        float2 t0 = __bfloat1622float2(tp[0]);
        float2 t1 = __bfloat1622float2(tp[1]);
        float2 t2 = __bfloat1622float2(tp[2]);
        float2 t3 = __bfloat1622float2(tp[3]);
        float d0 = f0.x + c0.x - t0.x; ss += d0 * d0;
        float d1 = f0.y + c0.y - t0.y; ss += d1 * d1;
        float d2 = f1.x + c0.z - t1.x; ss += d2 * d2;
        float d3 = f1.y + c0.w - t1.y; ss += d3 * d3;
        float d4 = f2.x + c1.x - t2.x; ss += d4 * d4;
        float d5 = f2.y + c1.y - t2.y; ss += d5 * d5;
        float d6 = f3.x + c1.z - t3.x; ss += d6 * d6;
        float d7 = f3.y + c1.w - t3.y; ss += d7 * d7;
    }
    #pragma unroll
    for (int off = 16; off > 0; off >>= 1)
        ss += __shfl_xor_sync(0xffffffffu, ss, off);
    __shared__ float swarp[8];
    if (lane == 0) swarp[w] = ss;
    __syncthreads();
    if (tid == 0) {
        double tot = 0.0;
        #pragma unroll
        for (int i = 0; i < 8; i++) tot += (double)swarp[i];
        atomicAdd(&g_sq, tot);
        __threadfence();
        int done = atomicAdd(&g_done, 1);
        if (done == Bb * 8 - 1) {
            double sq = atomicAdd(&g_sq, 0.0);
            double kl = atomicAdd(&g_kl, 0.0);
            int valid = atomicAdd(&g_valid, 0);
            long long denom = (long long)valid * (long long)Dd;
            if (denom < 1) denom = 1;
            out[0] = (float)(sq / (double)denom);
            out[1] = (float)(-0.5 * kl / (double)Bb);
        }
    }
}

// ---------------- launch ----------------------------------------------------
extern "C" void kernel_launch(void* const* d_in, const int* in_sizes, int n_in,
                              void* d_out, int out_size) {
    (void)in_sizes; (void)n_in; (void)out_size;
    const int*   vocab = (const int*)d_in[0];
    const int*   order = (const int*)d_in[1];
    const void*  mask  = d_in[2];
    const float* eps   = (const float*)d_in[3];
    const float* emb   = (const float*)d_in[4];
    const float* Wm    = (const float*)d_in[5];
    const float* bm    = (const float*)d_in[6];
    const float* Wv    = (const float*)d_in[7];
    const float* bv    = (const float*)d_in[8];
    const float* Wlin  = (const float*)d_in[9];
    const float* blin  = (const float*)d_in[10];
    const float* Wout  = (const float*)d_in[11];
    const float* bout  = (const float*)d_in[12];
    float* out = (float*)d_out;

    static cudaStream_t s2 = nullptr;
    static cudaEvent_t ev_fork = nullptr, ev_join = nullptr;
    static int configured = 0;
    if (!configured) {
        cudaFuncSetAttribute(gemm_mma, cudaFuncAttributeMaxDynamicSharedMemorySize, SMEM_GEMM);
        cudaStreamCreateWithFlags(&s2, cudaStreamNonBlocking);
        cudaEventCreateWithFlags(&ev_fork, cudaEventDisableTiming);
        cudaEventCreateWithFlags(&ev_join, cudaEventDisableTiming);
        configured = 1;
    }

    cudaEventRecord(ev_fork, 0);

    // side stream: k0 + enc chain (independent of GEMM)
    cudaStreamWaitEvent(s2, ev_fork, 0);
    k0_detect<<<64, 256, 0, s2>>>((const unsigned*)mask);
    enc_par<<<dim3(Bb, 8), 256, 0, s2>>>(vocab, order, mask, emb);
    klat_kernel<<<Bb, 256, 0, s2>>>(eps, Wm, bm, Wv, bv, Wlin, blin, Wout, bout);
    cudaEventRecord(ev_join, s2);

    // main stream: GEMM path
    gemm_mma<<<(Vv + 127) / 128, 512, SMEM_GEMM>>>(emb, Wout);

    cudaStreamWaitEvent(0, ev_join, 0);
    loss_kernel<<<dim3(Bb, 8), 256>>>(vocab, out);
}